// round 1
// baseline (speedup 1.0000x reference)
#include <cuda_runtime.h>
#include <cuda_bf16.h>
#include <math.h>

// Problem dims
#define BATCH   8
#define S_LEN   1024
#define DMODEL  2048
#define HEADS   16
#define HD      128
#define MTOK    (BATCH * S_LEN)          // 8192 token rows

// ---------------- scratch (device globals; no allocations allowed) ----------
__device__ float g_Q[(size_t)MTOK * DMODEL];
__device__ float g_K[(size_t)MTOK * DMODEL];
__device__ float g_V[(size_t)MTOK * DMODEL];
__device__ float g_CTX[(size_t)MTOK * DMODEL];

// ---------------- SGEMM: C[M,N] = alpha * A[M,K] @ B[K,N] -------------------
// 128x128 block tile, BK=8, 256 threads, 8x8 per-thread tile.
#define GBM 128
#define GBN 128
#define GBK 8
#define BS_STRIDE 132   // padded row stride for B tile (floats, /4 aligned)

__global__ void __launch_bounds__(256) sgemm128(const float* __restrict__ A,
                                                const float* __restrict__ B,
                                                float* __restrict__ C,
                                                int M, int N, int K, float alpha)
{
    __shared__ float As[GBK][GBM];
    __shared__ float Bs[GBK][BS_STRIDE];

    const int tid  = threadIdx.x;
    const int row0 = blockIdx.y * GBM;
    const int col0 = blockIdx.x * GBN;
    const int ty   = tid >> 4;     // 0..15
    const int tx   = tid & 15;     // 0..15

    // load assignments
    const int arow = tid >> 1;            // 0..127
    const int acol = (tid & 1) * 4;       // 0 or 4
    const int brow = tid >> 5;            // 0..7
    const int bcol = (tid & 31) * 4;      // 0..124

    const float* Aptr = A + (size_t)(row0 + arow) * K + acol;
    const float* Bptr = B + (size_t)brow * N + col0 + bcol;

    float acc[8][8];
#pragma unroll
    for (int i = 0; i < 8; i++)
#pragma unroll
        for (int j = 0; j < 8; j++) acc[i][j] = 0.f;

    for (int kk = 0; kk < K; kk += GBK) {
        float4 av = *(const float4*)(Aptr + kk);
        float4 bv = *(const float4*)(Bptr + (size_t)kk * N);
        As[acol + 0][arow] = av.x;
        As[acol + 1][arow] = av.y;
        As[acol + 2][arow] = av.z;
        As[acol + 3][arow] = av.w;
        *(float4*)&Bs[brow][bcol] = bv;
        __syncthreads();

#pragma unroll
        for (int k = 0; k < GBK; k++) {
            float4 a0 = *(const float4*)&As[k][ty * 8];
            float4 a1 = *(const float4*)&As[k][ty * 8 + 4];
            float4 b0 = *(const float4*)&Bs[k][tx * 8];
            float4 b1 = *(const float4*)&Bs[k][tx * 8 + 4];
            float a[8] = {a0.x, a0.y, a0.z, a0.w, a1.x, a1.y, a1.z, a1.w};
            float b[8] = {b0.x, b0.y, b0.z, b0.w, b1.x, b1.y, b1.z, b1.w};
#pragma unroll
            for (int i = 0; i < 8; i++)
#pragma unroll
                for (int j = 0; j < 8; j++)
                    acc[i][j] = fmaf(a[i], b[j], acc[i][j]);
        }
        __syncthreads();
    }

#pragma unroll
    for (int i = 0; i < 8; i++) {
        float* crow = C + (size_t)(row0 + ty * 8 + i) * N + col0 + tx * 8;
        float4 v0 = make_float4(alpha * acc[i][0], alpha * acc[i][1],
                                alpha * acc[i][2], alpha * acc[i][3]);
        float4 v1 = make_float4(alpha * acc[i][4], alpha * acc[i][5],
                                alpha * acc[i][6], alpha * acc[i][7]);
        *(float4*)crow       = v0;
        *(float4*)(crow + 4) = v1;
    }
}

// ---------------- Flash attention (fp32, online softmax) --------------------
// One block per (q-tile of 64, head, batch). 256 threads.
#define BQ 64
#define BK 64
#define QK_STRIDE 129   // Q/K smem row stride (scalar access; stride%32==1 -> <=2-way conflicts)
#define VS_STRIDE 132   // V smem row stride (float4 aligned)
#define SS_STRIDE 65    // scores row stride

#define ATTN_SMEM_FLOATS (BQ*QK_STRIDE + BK*QK_STRIDE + BK*VS_STRIDE + BQ*SS_STRIDE + 3*BQ)
#define ATTN_SMEM_BYTES  (ATTN_SMEM_FLOATS * 4)

__global__ void __launch_bounds__(256) attn_kernel(const float* __restrict__ Q,
                                                   const float* __restrict__ K,
                                                   const float* __restrict__ V,
                                                   float* __restrict__ O)
{
    extern __shared__ float sm[];
    float* Qs   = sm;                              // BQ x 129
    float* Ks   = Qs + BQ * QK_STRIDE;             // BK x 129
    float* Vs   = Ks + BK * QK_STRIDE;             // BK x 132 (float4 aligned offset)
    float* Ss   = Vs + BK * VS_STRIDE;             // BQ x 65
    float* rowm = Ss + BQ * SS_STRIDE;
    float* rowl = rowm + BQ;
    float* rowc = rowl + BQ;

    const int tid = threadIdx.x;
    const int q0  = blockIdx.x * BQ;
    const int h   = blockIdx.y;
    const int b   = blockIdx.z;

    const size_t base = ((size_t)b * S_LEN) * DMODEL + (size_t)h * HD;

    // load Q tile (coalesced: one warp covers one 512B row segment)
#pragma unroll
    for (int i = 0; i < 8; i++) {
        int id = i * 256 + tid;
        int r  = id >> 5;
        int d4 = (id & 31) * 4;
        float4 v = *(const float4*)(Q + base + (size_t)(q0 + r) * DMODEL + d4);
        float* dst = Qs + r * QK_STRIDE + d4;
        dst[0] = v.x; dst[1] = v.y; dst[2] = v.z; dst[3] = v.w;
    }
    if (tid < BQ) { rowm[tid] = -1e30f; rowl[tid] = 0.f; }

    float o[32];
#pragma unroll
    for (int i = 0; i < 32; i++) o[i] = 0.f;

    const int sty  = tid >> 4, stx = tid & 15;   // score tile mapping (4x4 each)
    const int orow = tid >> 2, ocb = tid & 3;    // O mapping: row, 32-col block

    for (int kt = 0; kt < S_LEN; kt += BK) {
        __syncthreads();   // previous-iter consumers of Ks/Vs are done
        // load K and V tiles
#pragma unroll
        for (int i = 0; i < 8; i++) {
            int id = i * 256 + tid;
            int r  = id >> 5;
            int d4 = (id & 31) * 4;
            float4 kf = *(const float4*)(K + base + (size_t)(kt + r) * DMODEL + d4);
            float* kd = Ks + r * QK_STRIDE + d4;
            kd[0] = kf.x; kd[1] = kf.y; kd[2] = kf.z; kd[3] = kf.w;
            float4 vf = *(const float4*)(V + base + (size_t)(kt + r) * DMODEL + d4);
            *(float4*)(Vs + r * VS_STRIDE + d4) = vf;
        }
        __syncthreads();

        // scores: each thread computes a 4x4 patch of the 64x64 tile
        float s[4][4];
#pragma unroll
        for (int i = 0; i < 4; i++)
#pragma unroll
            for (int j = 0; j < 4; j++) s[i][j] = 0.f;

        for (int k = 0; k < HD; k++) {
            float qv[4], kv[4];
#pragma unroll
            for (int i = 0; i < 4; i++) qv[i] = Qs[(sty * 4 + i) * QK_STRIDE + k];
#pragma unroll
            for (int j = 0; j < 4; j++) kv[j] = Ks[(stx * 4 + j) * QK_STRIDE + k];
#pragma unroll
            for (int i = 0; i < 4; i++)
#pragma unroll
                for (int j = 0; j < 4; j++)
                    s[i][j] = fmaf(qv[i], kv[j], s[i][j]);
        }
#pragma unroll
        for (int i = 0; i < 4; i++)
#pragma unroll
            for (int j = 0; j < 4; j++)
                Ss[(sty * 4 + i) * SS_STRIDE + stx * 4 + j] = s[i][j];
        __syncthreads();

        // per-row online softmax (64 active threads)
        if (tid < BQ) {
            float* srow = Ss + tid * SS_STRIDE;
            float m = rowm[tid];
            float mt = m;
#pragma unroll 8
            for (int j = 0; j < BK; j++) mt = fmaxf(mt, srow[j]);
            float corr = __expf(m - mt);
            float l = rowl[tid] * corr;
#pragma unroll 8
            for (int j = 0; j < BK; j++) {
                float p = __expf(srow[j] - mt);
                srow[j] = p;
                l += p;
            }
            rowm[tid] = mt; rowl[tid] = l; rowc[tid] = corr;
        }
        __syncthreads();

        // O update: each thread owns (row orow, cols ocb*32 .. +31)
        {
            float corr = rowc[orow];
#pragma unroll
            for (int i = 0; i < 32; i++) o[i] *= corr;
            const float* srow = Ss + orow * SS_STRIDE;
            for (int j = 0; j < BK; j++) {
                float p = srow[j];
                const float* vrow = Vs + j * VS_STRIDE + ocb * 32;
#pragma unroll
                for (int i = 0; i < 32; i++)
                    o[i] = fmaf(p, vrow[i], o[i]);
            }
        }
    }
    __syncthreads();

    // normalize, stage through shared (reuse Vs region, stride 128), coalesced store
    {
        float inv = 1.f / rowl[orow];
        float* dst = Vs + orow * HD + ocb * 32;
#pragma unroll
        for (int i = 0; i < 32; i++) dst[i] = o[i] * inv;
    }
    __syncthreads();
#pragma unroll
    for (int i = 0; i < 8; i++) {
        int id = i * 256 + tid;
        int r  = id >> 5;
        int d4 = (id & 31) * 4;
        float4 v = *(const float4*)(Vs + r * HD + d4);
        *(float4*)(O + base + (size_t)(q0 + r) * DMODEL + d4) = v;
    }
}

// ---------------- launch ----------------------------------------------------
extern "C" void kernel_launch(void* const* d_in, const int* in_sizes, int n_in,
                              void* d_out, int out_size)
{
    const float* inputs_q  = (const float*)d_in[0];
    const float* inputs_kv = (const float*)d_in[1];
    const float* Wq        = (const float*)d_in[2];
    const float* Wk        = (const float*)d_in[3];
    const float* Wv        = (const float*)d_in[4];
    const float* Wo        = (const float*)d_in[5];
    float* out             = (float*)d_out;

    float *qb, *kb, *vb, *cb;
    cudaGetSymbolAddress((void**)&qb, g_Q);
    cudaGetSymbolAddress((void**)&kb, g_K);
    cudaGetSymbolAddress((void**)&vb, g_V);
    cudaGetSymbolAddress((void**)&cb, g_CTX);

    cudaFuncSetAttribute(attn_kernel, cudaFuncAttributeMaxDynamicSharedMemorySize,
                         ATTN_SMEM_BYTES);

    const float qscale = 0.08838834764831845f;   // 1/sqrt(128)

    dim3 gemm_grid(DMODEL / GBN, MTOK / GBM);    // (16, 64)
    sgemm128<<<gemm_grid, 256>>>(inputs_q,  Wq, qb, MTOK, DMODEL, DMODEL, qscale);
    sgemm128<<<gemm_grid, 256>>>(inputs_kv, Wk, kb, MTOK, DMODEL, DMODEL, 1.0f);
    sgemm128<<<gemm_grid, 256>>>(inputs_kv, Wv, vb, MTOK, DMODEL, DMODEL, 1.0f);

    dim3 attn_grid(S_LEN / BQ, HEADS, BATCH);    // (16, 16, 8)
    attn_kernel<<<attn_grid, 256, ATTN_SMEM_BYTES>>>(qb, kb, vb, cb);

    sgemm128<<<gemm_grid, 256>>>(cb, Wo, out, MTOK, DMODEL, DMODEL, 1.0f);
}

// round 3
// speedup vs baseline: 2.5580x; 2.5580x over previous
#include <cuda_runtime.h>
#include <cuda_bf16.h>
#include <cstdint>
#include <math.h>

// Problem dims
#define BATCH   8
#define S_LEN   1024
#define DMODEL  2048
#define HEADS   16
#define HD      128
#define MTOK    (BATCH * S_LEN)          // 8192 token rows
#define KP      (3 * DMODEL)             // stacked split-K: 6144

// ---------------- scratch (device globals; no allocations allowed) ----------
__device__ float g_Q  [(size_t)MTOK * DMODEL];
__device__ float g_K  [(size_t)MTOK * DMODEL];
__device__ float g_V  [(size_t)MTOK * DMODEL];
__device__ float g_CTX[(size_t)MTOK * DMODEL];
__device__ __align__(16) __nv_bfloat16 g_Aq  [(size_t)MTOK * KP];   // [A_hi | A_lo | A_hi]
__device__ __align__(16) __nv_bfloat16 g_Akv [(size_t)MTOK * KP];
__device__ __align__(16) __nv_bfloat16 g_Actx[(size_t)MTOK * KP];
__device__ __align__(16) __nv_bfloat16 g_Wqt [(size_t)DMODEL * KP]; // [n][ B_hi | B_hi | B_lo ]
__device__ __align__(16) __nv_bfloat16 g_Wkt [(size_t)DMODEL * KP];
__device__ __align__(16) __nv_bfloat16 g_Wvt [(size_t)DMODEL * KP];
__device__ __align__(16) __nv_bfloat16 g_Wot [(size_t)DMODEL * KP];

// ===================== PTX helpers ==========================================
__device__ __forceinline__ uint32_t smem_u32(const void* p) {
    uint32_t a;
    asm("{ .reg .u64 t; cvta.to.shared.u64 t, %1; cvt.u32.u64 %0, t; }" : "=r"(a) : "l"(p));
    return a;
}
__device__ __forceinline__ void cpasync16(uint32_t dst, const void* src) {
    asm volatile("cp.async.cg.shared.global [%0], [%1], 16;" :: "r"(dst), "l"(src) : "memory");
}
template <int N> __device__ __forceinline__ void cpwait() {
    asm volatile("cp.async.wait_group %0;" :: "n"(N) : "memory");
}
#define CPCOMMIT() asm volatile("cp.async.commit_group;" ::: "memory")

__device__ __forceinline__ void ldsm_x4(uint32_t* r, uint32_t addr) {
    asm volatile("ldmatrix.sync.aligned.m8n8.x4.shared.b16 {%0,%1,%2,%3}, [%4];"
        : "=r"(r[0]), "=r"(r[1]), "=r"(r[2]), "=r"(r[3]) : "r"(addr));
}
__device__ __forceinline__ void mma16816(float* c, const uint32_t* a, uint32_t b0, uint32_t b1) {
    asm volatile("mma.sync.aligned.m16n8k16.row.col.f32.bf16.bf16.f32 "
        "{%0,%1,%2,%3}, {%4,%5,%6,%7}, {%8,%9}, {%0,%1,%2,%3};"
        : "+f"(c[0]), "+f"(c[1]), "+f"(c[2]), "+f"(c[3])
        : "r"(a[0]), "r"(a[1]), "r"(a[2]), "r"(a[3]), "r"(b0), "r"(b1));
}

// ===================== bf16 split-K mma.sync GEMM ===========================
// C[M,N] = alpha * Ahat[M,KP] * Bhat[N,KP]^T   (both K-major bf16, KP=6144)
#define TBM 128
#define TBN 128
#define TBK 64
#define NITER (KP / TBK)              // 96
#define ROW_B 144                     // smem row stride in bytes (64 bf16 + 8 pad)
#define ATILE (128 * ROW_B)           // 18432
#define STAGE (2 * ATILE)             // 36864 (A then B)
#define GEMM_SMEM (2 * STAGE)         // 73728

__global__ void __launch_bounds__(256, 2) gemm_bf16_mma(const __nv_bfloat16* __restrict__ A,
                                                        const __nv_bfloat16* __restrict__ B,
                                                        float* __restrict__ C,
                                                        int N, float alpha)
{
    extern __shared__ char smc[];
    const uint32_t smem = smem_u32(smc);
    const int tid  = threadIdx.x;
    const int lane = tid & 31;
    const int wid  = tid >> 5;
    const int wm   = wid >> 2;        // 0..1 (64-row slab)
    const int wn   = wid & 3;         // 0..3 (32-col slab)

    const int m0 = blockIdx.y * TBM;
    const int n0 = blockIdx.x * TBN;

    float acc[4][4][4];
#pragma unroll
    for (int mi = 0; mi < 4; mi++)
#pragma unroll
        for (int ni = 0; ni < 4; ni++)
#pragma unroll
            for (int e = 0; e < 4; e++) acc[mi][ni][e] = 0.f;

    // stage loader: 2048 x 16B chunks (A:1024, B:1024), 8 per thread
    auto load_stage = [&](int buf, int k0) {
#pragma unroll
        for (int t = 0; t < 8; t++) {
            int c   = tid + t * 256;
            int isB = c >> 10;
            int cc  = c & 1023;
            int row = cc >> 3, q = cc & 7;
            uint32_t off = (uint32_t)(isB ? ATILE : 0) + (uint32_t)(row * ROW_B + q * 16);
            const __nv_bfloat16* g = isB ? (B + (size_t)(n0 + row) * KP + k0 + q * 8)
                                         : (A + (size_t)(m0 + row) * KP + k0 + q * 8);
            cpasync16(smem + buf * STAGE + off, g);
        }
        CPCOMMIT();
    };

    load_stage(0, 0);

    for (int i = 0; i < NITER; i++) {
        const int buf = i & 1;
        if (i + 1 < NITER) { load_stage(buf ^ 1, (i + 1) * TBK); cpwait<1>(); }
        else               { cpwait<0>(); }
        __syncthreads();

        const uint32_t sa = smem + buf * STAGE + (uint32_t)(wm * 64) * ROW_B;
        const uint32_t sb = smem + buf * STAGE + ATILE + (uint32_t)(wn * 32) * ROW_B;

#pragma unroll
        for (int kh = 0; kh < 2; kh++) {          // two k32 halves
            uint32_t bfr[4][4];
#pragma unroll
            for (int ni = 0; ni < 4; ni++)
                ldsm_x4(bfr[ni], sb + (uint32_t)((ni * 8 + (lane & 7)) * ROW_B
                                                 + (kh * 32 + (lane >> 3) * 8) * 2));
#pragma unroll
            for (int kq = 0; kq < 2; kq++) {      // k16 steps within half
                uint32_t afr[4][4];
#pragma unroll
                for (int mi = 0; mi < 4; mi++)
                    ldsm_x4(afr[mi], sa + (uint32_t)((mi * 16 + (lane & 15)) * ROW_B
                                                     + (kh * 32 + kq * 16 + (lane >> 4) * 8) * 2));
#pragma unroll
                for (int mi = 0; mi < 4; mi++)
#pragma unroll
                    for (int ni = 0; ni < 4; ni++)
                        mma16816(acc[mi][ni], afr[mi], bfr[ni][2 * kq], bfr[ni][2 * kq + 1]);
            }
        }
        __syncthreads();
    }

    // epilogue: direct float2 stores
#pragma unroll
    for (int mi = 0; mi < 4; mi++) {
#pragma unroll
        for (int ni = 0; ni < 4; ni++) {
            int r = m0 + wm * 64 + mi * 16 + (lane >> 2);
            int c = n0 + wn * 32 + ni * 8 + (lane & 3) * 2;
            float2 v0 = make_float2(alpha * acc[mi][ni][0], alpha * acc[mi][ni][1]);
            float2 v1 = make_float2(alpha * acc[mi][ni][2], alpha * acc[mi][ni][3]);
            *(float2*)(C + (size_t)r * N + c)       = v0;
            *(float2*)(C + (size_t)(r + 8) * N + c) = v1;
        }
    }
}

// ===================== fp32 -> bf16 hi/lo split conversions =================
__global__ void __launch_bounds__(256) conv_act(const float* __restrict__ X,
                                                __nv_bfloat16* __restrict__ Y)
{
    size_t idx = (size_t)blockIdx.x * 256 + threadIdx.x;   // over MTOK*DMODEL
    float x = X[idx];
    __nv_bfloat16 hi = __float2bfloat16(x);
    __nv_bfloat16 lo = __float2bfloat16(x - __bfloat162float(hi));
    size_t row = idx >> 11;
    size_t col = idx & 2047;
    size_t base = row * KP;
    Y[base + col] = hi;
    Y[base + DMODEL + col] = lo;
    Y[base + 2 * DMODEL + col] = hi;
}

// W[k][n] (2048x2048) -> Wt[n][ hi(k) | hi(k) | lo(k) ]  (transpose + split)
__global__ void __launch_bounds__(256) conv_wt(const float* __restrict__ W,
                                               __nv_bfloat16* __restrict__ Wt)
{
    __shared__ float tile[32][33];
    const int k0 = blockIdx.y * 32, n0 = blockIdx.x * 32;
    const int tx = threadIdx.x, ty = threadIdx.y;     // (32, 8)
#pragma unroll
    for (int i = 0; i < 4; i++)
        tile[ty + i * 8][tx] = W[(size_t)(k0 + ty + i * 8) * DMODEL + n0 + tx];
    __syncthreads();
#pragma unroll
    for (int i = 0; i < 4; i++) {
        int n = n0 + ty + i * 8;
        int k = k0 + tx;
        float x = tile[tx][ty + i * 8];
        __nv_bfloat16 hi = __float2bfloat16(x);
        __nv_bfloat16 lo = __float2bfloat16(x - __bfloat162float(hi));
        size_t base = (size_t)n * KP;
        Wt[base + k] = hi;
        Wt[base + DMODEL + k] = hi;
        Wt[base + 2 * DMODEL + k] = lo;
    }
}

// ---------------- Flash attention (fp32, online softmax) --------------------
#define BQ 64
#define BK 64
#define QK_STRIDE 130   // even -> float2 along k
#define VS_STRIDE 132
#define SS_STRIDE 66    // even -> float2 along j

#define ATTN_SMEM_FLOATS (BQ*QK_STRIDE + BK*QK_STRIDE + BK*VS_STRIDE + BQ*SS_STRIDE + 3*BQ)
#define ATTN_SMEM_BYTES  (ATTN_SMEM_FLOATS * 4)

__global__ void __launch_bounds__(256) attn_kernel(const float* __restrict__ Q,
                                                   const float* __restrict__ K,
                                                   const float* __restrict__ V,
                                                   float* __restrict__ O)
{
    extern __shared__ float sm[];
    float* Qs   = sm;
    float* Ks   = Qs + BQ * QK_STRIDE;
    float* Vs   = Ks + BK * QK_STRIDE;
    float* Ss   = Vs + BK * VS_STRIDE;
    float* rowm = Ss + BQ * SS_STRIDE;
    float* rowl = rowm + BQ;
    float* rowc = rowl + BQ;

    const int tid = threadIdx.x;
    const int q0  = blockIdx.x * BQ;
    const int h   = blockIdx.y;
    const int b   = blockIdx.z;

    const size_t base = ((size_t)b * S_LEN) * DMODEL + (size_t)h * HD;

    // tile mappings: 4 rows x 8 cols per thread (scores use 4x4 patch of 64x64)
    const int rg = tid & 15;          // row group: rows rg*4 .. +3
    const int cg = tid >> 4;          // col group: cols cg*8 .. +7 (for V/O; cg*4 for scores)

#pragma unroll
    for (int i = 0; i < 8; i++) {
        int id = i * 256 + tid;
        int r  = id >> 5;
        int d4 = (id & 31) * 4;
        float4 v = *(const float4*)(Q + base + (size_t)(q0 + r) * DMODEL + d4);
        float* dst = Qs + r * QK_STRIDE + d4;
        dst[0] = v.x; dst[1] = v.y; dst[2] = v.z; dst[3] = v.w;
    }
    if (tid < BQ) { rowm[tid] = -1e30f; rowl[tid] = 0.f; }

    float o[4][8];
#pragma unroll
    for (int i = 0; i < 4; i++)
#pragma unroll
        for (int j = 0; j < 8; j++) o[i][j] = 0.f;

    for (int kt = 0; kt < S_LEN; kt += BK) {
        __syncthreads();
#pragma unroll
        for (int i = 0; i < 8; i++) {
            int id = i * 256 + tid;
            int r  = id >> 5;
            int d4 = (id & 31) * 4;
            float4 kf = *(const float4*)(K + base + (size_t)(kt + r) * DMODEL + d4);
            float* kd = Ks + r * QK_STRIDE + d4;
            kd[0] = kf.x; kd[1] = kf.y; kd[2] = kf.z; kd[3] = kf.w;
            float4 vf = *(const float4*)(V + base + (size_t)(kt + r) * DMODEL + d4);
            *(float4*)(Vs + r * VS_STRIDE + d4) = vf;
        }
        __syncthreads();

        // scores: 4x4 patch per thread, float2 along k
        {
            float s[4][4];
#pragma unroll
            for (int i = 0; i < 4; i++)
#pragma unroll
                for (int j = 0; j < 4; j++) s[i][j] = 0.f;

            const int sq = rg * 4;       // 4 score rows
            const int sk = cg * 4;       // 4 score cols
            for (int k = 0; k < HD; k += 2) {
                float2 qv[4], kv[4];
#pragma unroll
                for (int i = 0; i < 4; i++) qv[i] = *(const float2*)&Qs[(sq + i) * QK_STRIDE + k];
#pragma unroll
                for (int j = 0; j < 4; j++) kv[j] = *(const float2*)&Ks[(sk + j) * QK_STRIDE + k];
#pragma unroll
                for (int i = 0; i < 4; i++)
#pragma unroll
                    for (int j = 0; j < 4; j++)
                        s[i][j] = fmaf(qv[i].y, kv[j].y, fmaf(qv[i].x, kv[j].x, s[i][j]));
            }
#pragma unroll
            for (int i = 0; i < 4; i++)
#pragma unroll
                for (int j = 0; j < 4; j++)
                    Ss[(sq + i) * SS_STRIDE + sk + j] = s[i][j];
        }
        __syncthreads();

        // per-row online softmax (64 active threads)
        if (tid < BQ) {
            float* srow = Ss + tid * SS_STRIDE;
            float m = rowm[tid];
            float mt = m;
#pragma unroll 8
            for (int j = 0; j < BK; j++) mt = fmaxf(mt, srow[j]);
            float corr = __expf(m - mt);
            float l = rowl[tid] * corr;
#pragma unroll 8
            for (int j = 0; j < BK; j++) {
                float p = __expf(srow[j] - mt);
                srow[j] = p;
                l += p;
            }
            rowm[tid] = mt; rowl[tid] = l; rowc[tid] = corr;
        }
        __syncthreads();

        // O update: 4 rows (rg*4..) x 8 cols (cg*8..) per thread
        {
            float corr[4];
#pragma unroll
            for (int rr = 0; rr < 4; rr++) corr[rr] = rowc[rg * 4 + rr];
#pragma unroll
            for (int rr = 0; rr < 4; rr++)
#pragma unroll
                for (int c = 0; c < 8; c++) o[rr][c] *= corr[rr];

            for (int j = 0; j < BK; j += 2) {
                float2 p2[4];
#pragma unroll
                for (int rr = 0; rr < 4; rr++)
                    p2[rr] = *(const float2*)&Ss[(rg * 4 + rr) * SS_STRIDE + j];
                float2 va[4], vb[4];
#pragma unroll
                for (int c = 0; c < 4; c++) {
                    va[c] = *(const float2*)&Vs[j * VS_STRIDE + cg * 8 + c * 2];
                    vb[c] = *(const float2*)&Vs[(j + 1) * VS_STRIDE + cg * 8 + c * 2];
                }
#pragma unroll
                for (int rr = 0; rr < 4; rr++)
#pragma unroll
                    for (int c = 0; c < 4; c++) {
                        o[rr][2 * c]     = fmaf(p2[rr].x, va[c].x, o[rr][2 * c]);
                        o[rr][2 * c]     = fmaf(p2[rr].y, vb[c].x, o[rr][2 * c]);
                        o[rr][2 * c + 1] = fmaf(p2[rr].x, va[c].y, o[rr][2 * c + 1]);
                        o[rr][2 * c + 1] = fmaf(p2[rr].y, vb[c].y, o[rr][2 * c + 1]);
                    }
            }
        }
    }
    __syncthreads();

    // normalize, stage through shared, coalesced store
#pragma unroll
    for (int rr = 0; rr < 4; rr++) {
        float inv = 1.f / rowl[rg * 4 + rr];
        float* dst = Vs + (rg * 4 + rr) * VS_STRIDE + cg * 8;
#pragma unroll
        for (int c = 0; c < 8; c++) dst[c] = o[rr][c] * inv;
    }
    __syncthreads();
#pragma unroll
    for (int i = 0; i < 8; i++) {
        int id = i * 256 + tid;
        int r  = id >> 5;
        int d4 = (id & 31) * 4;
        float4 v = *(const float4*)(Vs + r * VS_STRIDE + d4);
        *(float4*)(O + base + (size_t)(q0 + r) * DMODEL + d4) = v;
    }
}

// ---------------- launch ----------------------------------------------------
extern "C" void kernel_launch(void* const* d_in, const int* in_sizes, int n_in,
                              void* d_out, int out_size)
{
    const float* inputs_q  = (const float*)d_in[0];
    const float* inputs_kv = (const float*)d_in[1];
    const float* Wq        = (const float*)d_in[2];
    const float* Wk        = (const float*)d_in[3];
    const float* Wv        = (const float*)d_in[4];
    const float* Wo        = (const float*)d_in[5];
    float* out             = (float*)d_out;

    float *qb, *kb, *vb, *cb;
    __nv_bfloat16 *aq, *akv, *actx, *wqt, *wkt, *wvt, *wot;
    cudaGetSymbolAddress((void**)&qb, g_Q);
    cudaGetSymbolAddress((void**)&kb, g_K);
    cudaGetSymbolAddress((void**)&vb, g_V);
    cudaGetSymbolAddress((void**)&cb, g_CTX);
    cudaGetSymbolAddress((void**)&aq,  g_Aq);
    cudaGetSymbolAddress((void**)&akv, g_Akv);
    cudaGetSymbolAddress((void**)&actx,g_Actx);
    cudaGetSymbolAddress((void**)&wqt, g_Wqt);
    cudaGetSymbolAddress((void**)&wkt, g_Wkt);
    cudaGetSymbolAddress((void**)&wvt, g_Wvt);
    cudaGetSymbolAddress((void**)&wot, g_Wot);

    cudaFuncSetAttribute(attn_kernel, cudaFuncAttributeMaxDynamicSharedMemorySize,
                         ATTN_SMEM_BYTES);
    cudaFuncSetAttribute(gemm_bf16_mma, cudaFuncAttributeMaxDynamicSharedMemorySize,
                         GEMM_SMEM);

    const float qscale = 0.08838834764831845f;   // 1/sqrt(128)

    // conversions
    conv_act<<<(MTOK * DMODEL) / 256, 256>>>(inputs_q,  aq);
    conv_act<<<(MTOK * DMODEL) / 256, 256>>>(inputs_kv, akv);
    dim3 wtg(64, 64), wtb(32, 8);
    conv_wt<<<wtg, wtb>>>(Wq, wqt);
    conv_wt<<<wtg, wtb>>>(Wk, wkt);
    conv_wt<<<wtg, wtb>>>(Wv, wvt);
    conv_wt<<<wtg, wtb>>>(Wo, wot);

    // projections on tensor cores (mma.sync bf16, split-K precision recovery)
    dim3 gg(DMODEL / TBN, MTOK / TBM);           // (16, 64)
    gemm_bf16_mma<<<gg, 256, GEMM_SMEM>>>(aq,  wqt, qb, DMODEL, qscale);
    gemm_bf16_mma<<<gg, 256, GEMM_SMEM>>>(akv, wkt, kb, DMODEL, 1.0f);
    gemm_bf16_mma<<<gg, 256, GEMM_SMEM>>>(akv, wvt, vb, DMODEL, 1.0f);

    dim3 attn_grid(S_LEN / BQ, HEADS, BATCH);    // (16, 16, 8)
    attn_kernel<<<attn_grid, 256, ATTN_SMEM_BYTES>>>(qb, kb, vb, cb);

    conv_act<<<(MTOK * DMODEL) / 256, 256>>>(cb, actx);
    gemm_bf16_mma<<<gg, 256, GEMM_SMEM>>>(actx, wot, out, DMODEL, 1.0f);
}

// round 4
// speedup vs baseline: 4.8379x; 1.8913x over previous
#include <cuda_runtime.h>
#include <cuda_bf16.h>
#include <cstdint>
#include <math.h>

// Problem dims
#define BATCH   8
#define S_LEN   1024
#define DMODEL  2048
#define HEADS   16
#define HD      128
#define MTOK    (BATCH * S_LEN)          // 8192 token rows
#define KP      (3 * DMODEL)             // stacked split-K: 6144

// ---------------- scratch (device globals; no allocations allowed) ----------
__device__ __align__(16) __nv_bfloat16 g_Aq  [(size_t)MTOK * KP];   // [A_hi | A_lo | A_hi]
__device__ __align__(16) __nv_bfloat16 g_Akv [(size_t)MTOK * KP];
__device__ __align__(16) __nv_bfloat16 g_Actx[(size_t)MTOK * KP];
__device__ __align__(16) __nv_bfloat16 g_Wqt [(size_t)DMODEL * KP]; // [n][ B_hi | B_hi | B_lo ]
__device__ __align__(16) __nv_bfloat16 g_Wkt [(size_t)DMODEL * KP];
__device__ __align__(16) __nv_bfloat16 g_Wvt [(size_t)DMODEL * KP];
__device__ __align__(16) __nv_bfloat16 g_Wot [(size_t)DMODEL * KP];
__device__ __align__(16) __nv_bfloat16 g_Qh [(size_t)MTOK * DMODEL];
__device__ __align__(16) __nv_bfloat16 g_Ql [(size_t)MTOK * DMODEL];
__device__ __align__(16) __nv_bfloat16 g_Kh [(size_t)MTOK * DMODEL];
__device__ __align__(16) __nv_bfloat16 g_Kl [(size_t)MTOK * DMODEL];
__device__ __align__(16) __nv_bfloat16 g_Vh [(size_t)MTOK * DMODEL];
__device__ __align__(16) __nv_bfloat16 g_Vl [(size_t)MTOK * DMODEL];

// ===================== PTX helpers ==========================================
__device__ __forceinline__ uint32_t smem_u32(const void* p) {
    uint32_t a;
    asm("{ .reg .u64 t; cvta.to.shared.u64 t, %1; cvt.u32.u64 %0, t; }" : "=r"(a) : "l"(p));
    return a;
}
__device__ __forceinline__ void cpasync16(uint32_t dst, const void* src) {
    asm volatile("cp.async.cg.shared.global [%0], [%1], 16;" :: "r"(dst), "l"(src) : "memory");
}
template <int N> __device__ __forceinline__ void cpwait() {
    asm volatile("cp.async.wait_group %0;" :: "n"(N) : "memory");
}
#define CPCOMMIT() asm volatile("cp.async.commit_group;" ::: "memory")

__device__ __forceinline__ void ldsm_x4(uint32_t* r, uint32_t addr) {
    asm volatile("ldmatrix.sync.aligned.m8n8.x4.shared.b16 {%0,%1,%2,%3}, [%4];"
        : "=r"(r[0]), "=r"(r[1]), "=r"(r[2]), "=r"(r[3]) : "r"(addr));
}
__device__ __forceinline__ void ldsm_x4_t(uint32_t* r, uint32_t addr) {
    asm volatile("ldmatrix.sync.aligned.m8n8.x4.trans.shared.b16 {%0,%1,%2,%3}, [%4];"
        : "=r"(r[0]), "=r"(r[1]), "=r"(r[2]), "=r"(r[3]) : "r"(addr));
}
__device__ __forceinline__ void mma16816(float* c, const uint32_t* a, uint32_t b0, uint32_t b1) {
    asm volatile("mma.sync.aligned.m16n8k16.row.col.f32.bf16.bf16.f32 "
        "{%0,%1,%2,%3}, {%4,%5,%6,%7}, {%8,%9}, {%0,%1,%2,%3};"
        : "+f"(c[0]), "+f"(c[1]), "+f"(c[2]), "+f"(c[3])
        : "r"(a[0]), "r"(a[1]), "r"(a[2]), "r"(a[3]), "r"(b0), "r"(b1));
}
__device__ __forceinline__ uint32_t pack_bf2(float x, float y) {
    __nv_bfloat162 h = __floats2bfloat162_rn(x, y);
    return *reinterpret_cast<uint32_t*>(&h);
}

// ===================== bf16 split-K mma.sync GEMM ===========================
// C[M,N] = alpha * Ahat[M,KP] * Bhat[N,KP]^T   (both K-major bf16, KP=6144)
#define TBM 128
#define TBN 128
#define TBK 64
#define NITER (KP / TBK)              // 96
#define ROW_B 144                     // smem row stride in bytes (64 bf16 + 8 pad)
#define ATILE (128 * ROW_B)           // 18432
#define STAGE (2 * ATILE)             // 36864 (A then B)
#define GEMM_SMEM (3 * STAGE)         // 110592, 3-stage

__global__ void __launch_bounds__(256, 2) gemm_bf16_mma(const __nv_bfloat16* __restrict__ A,
                                                        const __nv_bfloat16* __restrict__ B,
                                                        float* __restrict__ C,
                                                        __nv_bfloat16* __restrict__ Ch,
                                                        __nv_bfloat16* __restrict__ Cl,
                                                        int N, float alpha)
{
    extern __shared__ char smc[];
    const uint32_t smem = smem_u32(smc);
    const int tid  = threadIdx.x;
    const int lane = tid & 31;
    const int wid  = tid >> 5;
    const int wm   = wid >> 2;        // 0..1 (64-row slab)
    const int wn   = wid & 3;         // 0..3 (32-col slab)

    const int m0 = blockIdx.y * TBM;
    const int n0 = blockIdx.x * TBN;

    float acc[4][4][4];
#pragma unroll
    for (int mi = 0; mi < 4; mi++)
#pragma unroll
        for (int ni = 0; ni < 4; ni++)
#pragma unroll
            for (int e = 0; e < 4; e++) acc[mi][ni][e] = 0.f;

    auto load_stage = [&](int buf, int k0) {
#pragma unroll
        for (int t = 0; t < 8; t++) {
            int c   = tid + t * 256;
            int isB = c >> 10;
            int cc  = c & 1023;
            int row = cc >> 3, q = cc & 7;
            uint32_t off = (uint32_t)(isB ? ATILE : 0) + (uint32_t)(row * ROW_B + q * 16);
            const __nv_bfloat16* g = isB ? (B + (size_t)(n0 + row) * KP + k0 + q * 8)
                                         : (A + (size_t)(m0 + row) * KP + k0 + q * 8);
            cpasync16(smem + buf * STAGE + off, g);
        }
        CPCOMMIT();
    };

    load_stage(0, 0);
    load_stage(1, TBK);

    int buf = 0;
    for (int i = 0; i < NITER; i++) {
        if (i + 2 < NITER) { load_stage((buf + 2) % 3, (i + 2) * TBK); cpwait<2>(); }
        else if (i + 1 < NITER) cpwait<1>();
        else cpwait<0>();
        __syncthreads();

        const uint32_t sa = smem + buf * STAGE + (uint32_t)(wm * 64) * ROW_B;
        const uint32_t sb = smem + buf * STAGE + ATILE + (uint32_t)(wn * 32) * ROW_B;

#pragma unroll
        for (int kh = 0; kh < 2; kh++) {
            uint32_t bfr[4][4];
#pragma unroll
            for (int ni = 0; ni < 4; ni++)
                ldsm_x4(bfr[ni], sb + (uint32_t)((ni * 8 + (lane & 7)) * ROW_B
                                                 + (kh * 32 + (lane >> 3) * 8) * 2));
#pragma unroll
            for (int kq = 0; kq < 2; kq++) {
                uint32_t afr[4][4];
#pragma unroll
                for (int mi = 0; mi < 4; mi++)
                    ldsm_x4(afr[mi], sa + (uint32_t)((mi * 16 + (lane & 15)) * ROW_B
                                                     + (kh * 32 + kq * 16 + (lane >> 4) * 8) * 2));
#pragma unroll
                for (int mi = 0; mi < 4; mi++)
#pragma unroll
                    for (int ni = 0; ni < 4; ni++)
                        mma16816(acc[mi][ni], afr[mi], bfr[ni][2 * kq], bfr[ni][2 * kq + 1]);
            }
        }
        __syncthreads();
        buf = (buf + 1) % 3;
    }

    // epilogue
#pragma unroll
    for (int mi = 0; mi < 4; mi++) {
#pragma unroll
        for (int ni = 0; ni < 4; ni++) {
            int r = m0 + wm * 64 + mi * 16 + (lane >> 2);
            int c = n0 + wn * 32 + ni * 8 + (lane & 3) * 2;
            float v0 = alpha * acc[mi][ni][0], v1 = alpha * acc[mi][ni][1];
            float v2 = alpha * acc[mi][ni][2], v3 = alpha * acc[mi][ni][3];
            if (Ch) {
                __nv_bfloat162 h0 = __floats2bfloat162_rn(v0, v1);
                __nv_bfloat162 h1 = __floats2bfloat162_rn(v2, v3);
                __nv_bfloat162 l0 = __floats2bfloat162_rn(v0 - __bfloat162float(h0.x),
                                                          v1 - __bfloat162float(h0.y));
                __nv_bfloat162 l1 = __floats2bfloat162_rn(v2 - __bfloat162float(h1.x),
                                                          v3 - __bfloat162float(h1.y));
                *(__nv_bfloat162*)(Ch + (size_t)r * N + c)       = h0;
                *(__nv_bfloat162*)(Cl + (size_t)r * N + c)       = l0;
                *(__nv_bfloat162*)(Ch + (size_t)(r + 8) * N + c) = h1;
                *(__nv_bfloat162*)(Cl + (size_t)(r + 8) * N + c) = l1;
            } else {
                *(float2*)(C + (size_t)r * N + c)       = make_float2(v0, v1);
                *(float2*)(C + (size_t)(r + 8) * N + c) = make_float2(v2, v3);
            }
        }
    }
}

// ===================== fp32 -> bf16 hi/lo split conversions =================
__global__ void __launch_bounds__(256) conv_act(const float* __restrict__ X,
                                                __nv_bfloat16* __restrict__ Y)
{
    size_t idx = (size_t)blockIdx.x * 256 + threadIdx.x;
    float x = X[idx];
    __nv_bfloat16 hi = __float2bfloat16(x);
    __nv_bfloat16 lo = __float2bfloat16(x - __bfloat162float(hi));
    size_t row = idx >> 11;
    size_t col = idx & 2047;
    size_t base = row * KP;
    Y[base + col] = hi;
    Y[base + DMODEL + col] = lo;
    Y[base + 2 * DMODEL + col] = hi;
}

__global__ void __launch_bounds__(256) conv_wt(const float* __restrict__ W,
                                               __nv_bfloat16* __restrict__ Wt)
{
    __shared__ float tile[32][33];
    const int k0 = blockIdx.y * 32, n0 = blockIdx.x * 32;
    const int tx = threadIdx.x, ty = threadIdx.y;     // (32, 8)
#pragma unroll
    for (int i = 0; i < 4; i++)
        tile[ty + i * 8][tx] = W[(size_t)(k0 + ty + i * 8) * DMODEL + n0 + tx];
    __syncthreads();
#pragma unroll
    for (int i = 0; i < 4; i++) {
        int n = n0 + ty + i * 8;
        int k = k0 + tx;
        float x = tile[tx][ty + i * 8];
        __nv_bfloat16 hi = __float2bfloat16(x);
        __nv_bfloat16 lo = __float2bfloat16(x - __bfloat162float(hi));
        size_t base = (size_t)n * KP;
        Wt[base + k] = hi;
        Wt[base + DMODEL + k] = hi;
        Wt[base + 2 * DMODEL + k] = lo;
    }
}

// ============== Flash attention on tensor cores (bf16 3-term split) =========
// Grid (16,16,8); block 128 (4 warps, 16 q-rows each). BQ=64, BKT=64.
#define AT_STR 136                      // smem row stride (bf16), 272B
#define AT_TILE (64 * AT_STR)           // 8704 elems
#define ATTN_SMEM (6 * AT_TILE * 2)     // 104448 B: QH QL KH KL VH VL

__global__ void __launch_bounds__(128, 2) attn_mma(
    const __nv_bfloat16* __restrict__ Qh, const __nv_bfloat16* __restrict__ Ql,
    const __nv_bfloat16* __restrict__ Kh, const __nv_bfloat16* __restrict__ Kl,
    const __nv_bfloat16* __restrict__ Vh, const __nv_bfloat16* __restrict__ Vl,
    __nv_bfloat16* __restrict__ Actx)
{
    extern __shared__ char smc[];
    const uint32_t smem = smem_u32(smc);
    const int tid = threadIdx.x, lane = tid & 31, w = tid >> 5;
    const int q0 = blockIdx.x * 64, h = blockIdx.y, b = blockIdx.z;
    const size_t gbase = ((size_t)b * S_LEN) * DMODEL + (size_t)h * HD;
    const int qrow0 = w * 16;

    // load Q tiles once (hi, lo)
#pragma unroll
    for (int i = 0; i < 8; i++) {
        int id = tid + i * 128;
        int r = id >> 4, c = (id & 15) * 8;
        size_t g = gbase + (size_t)(q0 + r) * DMODEL + c;
        cpasync16(smem + (uint32_t)(0 * AT_TILE + r * AT_STR + c) * 2, Qh + g);
        cpasync16(smem + (uint32_t)(1 * AT_TILE + r * AT_STR + c) * 2, Ql + g);
    }
    CPCOMMIT();

    float m0 = -1e30f, m1 = -1e30f, l0 = 0.f, l1 = 0.f;
    float O[16][4];
#pragma unroll
    for (int i = 0; i < 16; i++)
#pragma unroll
        for (int e = 0; e < 4; e++) O[i][e] = 0.f;

    for (int kt = 0; kt < S_LEN / 64; kt++) {
        __syncthreads();    // previous iter consumers done before overwrite
#pragma unroll
        for (int i = 0; i < 8; i++) {
            int id = tid + i * 128;
            int r = id >> 4, c = (id & 15) * 8;
            size_t g = gbase + (size_t)(kt * 64 + r) * DMODEL + c;
            uint32_t so = (uint32_t)(r * AT_STR + c) * 2;
            cpasync16(smem + 2 * AT_TILE * 2 + so, Kh + g);
            cpasync16(smem + 3 * AT_TILE * 2 + so, Kl + g);
            cpasync16(smem + 4 * AT_TILE * 2 + so, Vh + g);
            cpasync16(smem + 5 * AT_TILE * 2 + so, Vl + g);
        }
        CPCOMMIT();
        cpwait<0>();
        __syncthreads();

        // ---- scores: S[16 x 64] per warp, 3-term split over k=HD ----
        float S[8][4];
#pragma unroll
        for (int ni = 0; ni < 8; ni++)
#pragma unroll
            for (int e = 0; e < 4; e++) S[ni][e] = 0.f;

#pragma unroll
        for (int kc = 0; kc < 24; kc++) {
            const int t  = kc >> 3;                 // 0: Qh*Kh 1: Ql*Kh 2: Qh*Kl
            const int k0 = (kc & 7) * 16;
            const uint32_t qtile = (t == 1) ? (uint32_t)(1 * AT_TILE) : 0u;
            const uint32_t ktile = (t == 2) ? (uint32_t)(3 * AT_TILE) : (uint32_t)(2 * AT_TILE);
            uint32_t aq[4];
            {
                int row = qrow0 + (lane & 15);
                int col = k0 + (lane >> 4) * 8;
                ldsm_x4(aq, smem + (qtile + row * AT_STR + col) * 2);
            }
#pragma unroll
            for (int nb = 0; nb < 4; nb++) {        // 16 keys per ldsm
                uint32_t bk[4];
                int row = nb * 16 + ((lane >> 4) & 1) * 8 + (lane & 7);
                int col = k0 + ((lane >> 3) & 1) * 8;
                ldsm_x4(bk, smem + (ktile + row * AT_STR + col) * 2);
                mma16816(S[2 * nb],     aq, bk[0], bk[1]);
                mma16816(S[2 * nb + 1], aq, bk[2], bk[3]);
            }
        }

        // ---- online softmax (rows r0=lane>>2, r1=r0+8) ----
        float mx0 = -1e30f, mx1 = -1e30f;
#pragma unroll
        for (int ni = 0; ni < 8; ni++) {
            mx0 = fmaxf(mx0, fmaxf(S[ni][0], S[ni][1]));
            mx1 = fmaxf(mx1, fmaxf(S[ni][2], S[ni][3]));
        }
        mx0 = fmaxf(mx0, __shfl_xor_sync(0xffffffff, mx0, 1));
        mx0 = fmaxf(mx0, __shfl_xor_sync(0xffffffff, mx0, 2));
        mx1 = fmaxf(mx1, __shfl_xor_sync(0xffffffff, mx1, 1));
        mx1 = fmaxf(mx1, __shfl_xor_sync(0xffffffff, mx1, 2));
        const float mn0 = fmaxf(m0, mx0), mn1 = fmaxf(m1, mx1);
        const float c0 = __expf(m0 - mn0), c1 = __expf(m1 - mn1);

        uint32_t Ph[16], Pl[16];
        float s0 = 0.f, s1 = 0.f;
#pragma unroll
        for (int ni = 0; ni < 8; ni++) {
            float p00 = __expf(S[ni][0] - mn0), p01 = __expf(S[ni][1] - mn0);
            float p10 = __expf(S[ni][2] - mn1), p11 = __expf(S[ni][3] - mn1);
            s0 += p00 + p01; s1 += p10 + p11;
            __nv_bfloat162 h0 = __floats2bfloat162_rn(p00, p01);
            __nv_bfloat162 h1 = __floats2bfloat162_rn(p10, p11);
            Ph[2 * ni]     = *reinterpret_cast<uint32_t*>(&h0);
            Ph[2 * ni + 1] = *reinterpret_cast<uint32_t*>(&h1);
            Pl[2 * ni]     = pack_bf2(p00 - __bfloat162float(h0.x), p01 - __bfloat162float(h0.y));
            Pl[2 * ni + 1] = pack_bf2(p10 - __bfloat162float(h1.x), p11 - __bfloat162float(h1.y));
        }
        s0 += __shfl_xor_sync(0xffffffff, s0, 1);
        s0 += __shfl_xor_sync(0xffffffff, s0, 2);
        s1 += __shfl_xor_sync(0xffffffff, s1, 1);
        s1 += __shfl_xor_sync(0xffffffff, s1, 2);
        l0 = l0 * c0 + s0; l1 = l1 * c1 + s1;
        m0 = mn0; m1 = mn1;

#pragma unroll
        for (int ni2 = 0; ni2 < 16; ni2++) {
            O[ni2][0] *= c0; O[ni2][1] *= c0;
            O[ni2][2] *= c1; O[ni2][3] *= c1;
        }

        // ---- PV: O[16 x 128] += Ph*Vh + Pl*Vh + Ph*Vl ----
#pragma unroll
        for (int kc2 = 0; kc2 < 4; kc2++) {
            uint32_t ah[4] = {Ph[4 * kc2], Ph[4 * kc2 + 1], Ph[4 * kc2 + 2], Ph[4 * kc2 + 3]};
            uint32_t al[4] = {Pl[4 * kc2], Pl[4 * kc2 + 1], Pl[4 * kc2 + 2], Pl[4 * kc2 + 3]};
            const int k0 = kc2 * 16;
            const int vrow = k0 + ((lane >> 3) & 1) * 8 + (lane & 7);
#pragma unroll
            for (int vb = 0; vb < 8; vb++) {
                uint32_t bv[4];
                int col = vb * 16 + ((lane >> 4) & 1) * 8;
                ldsm_x4_t(bv, smem + (uint32_t)(4 * AT_TILE + vrow * AT_STR + col) * 2);
                mma16816(O[2 * vb],     ah, bv[0], bv[1]);
                mma16816(O[2 * vb + 1], ah, bv[2], bv[3]);
                mma16816(O[2 * vb],     al, bv[0], bv[1]);
                mma16816(O[2 * vb + 1], al, bv[2], bv[3]);
            }
#pragma unroll
            for (int vb = 0; vb < 8; vb++) {
                uint32_t bv[4];
                int col = vb * 16 + ((lane >> 4) & 1) * 8;
                ldsm_x4_t(bv, smem + (uint32_t)(5 * AT_TILE + vrow * AT_STR + col) * 2);
                mma16816(O[2 * vb],     ah, bv[0], bv[1]);
                mma16816(O[2 * vb + 1], ah, bv[2], bv[3]);
            }
        }
    }

    // ---- epilogue: normalize, split to bf16 hi|lo|hi, write Actx ----
    const float inv0 = 1.f / l0, inv1 = 1.f / l1;
    const size_t tok0 = (size_t)b * S_LEN + q0 + qrow0 + (lane >> 2);
    const size_t tok1 = tok0 + 8;
#pragma unroll
    for (int ni2 = 0; ni2 < 16; ni2++) {
        int col = h * HD + ni2 * 8 + (lane & 3) * 2;
        float v00 = O[ni2][0] * inv0, v01 = O[ni2][1] * inv0;
        float v10 = O[ni2][2] * inv1, v11 = O[ni2][3] * inv1;
        __nv_bfloat162 h0 = __floats2bfloat162_rn(v00, v01);
        __nv_bfloat162 h1 = __floats2bfloat162_rn(v10, v11);
        __nv_bfloat162 lo0 = __floats2bfloat162_rn(v00 - __bfloat162float(h0.x),
                                                   v01 - __bfloat162float(h0.y));
        __nv_bfloat162 lo1 = __floats2bfloat162_rn(v10 - __bfloat162float(h1.x),
                                                   v11 - __bfloat162float(h1.y));
        __nv_bfloat16* a0 = Actx + tok0 * KP;
        __nv_bfloat16* a1 = Actx + tok1 * KP;
        *(__nv_bfloat162*)(a0 + col)              = h0;
        *(__nv_bfloat162*)(a0 + DMODEL + col)     = lo0;
        *(__nv_bfloat162*)(a0 + 2 * DMODEL + col) = h0;
        *(__nv_bfloat162*)(a1 + col)              = h1;
        *(__nv_bfloat162*)(a1 + DMODEL + col)     = lo1;
        *(__nv_bfloat162*)(a1 + 2 * DMODEL + col) = h1;
    }
}

// ---------------- launch ----------------------------------------------------
extern "C" void kernel_launch(void* const* d_in, const int* in_sizes, int n_in,
                              void* d_out, int out_size)
{
    const float* inputs_q  = (const float*)d_in[0];
    const float* inputs_kv = (const float*)d_in[1];
    const float* Wq        = (const float*)d_in[2];
    const float* Wk        = (const float*)d_in[3];
    const float* Wv        = (const float*)d_in[4];
    const float* Wo        = (const float*)d_in[5];
    float* out             = (float*)d_out;

    __nv_bfloat16 *aq, *akv, *actx, *wqt, *wkt, *wvt, *wot;
    __nv_bfloat16 *qh, *ql, *kh, *kl, *vh, *vl;
    cudaGetSymbolAddress((void**)&aq,  g_Aq);
    cudaGetSymbolAddress((void**)&akv, g_Akv);
    cudaGetSymbolAddress((void**)&actx,g_Actx);
    cudaGetSymbolAddress((void**)&wqt, g_Wqt);
    cudaGetSymbolAddress((void**)&wkt, g_Wkt);
    cudaGetSymbolAddress((void**)&wvt, g_Wvt);
    cudaGetSymbolAddress((void**)&wot, g_Wot);
    cudaGetSymbolAddress((void**)&qh, g_Qh);
    cudaGetSymbolAddress((void**)&ql, g_Ql);
    cudaGetSymbolAddress((void**)&kh, g_Kh);
    cudaGetSymbolAddress((void**)&kl, g_Kl);
    cudaGetSymbolAddress((void**)&vh, g_Vh);
    cudaGetSymbolAddress((void**)&vl, g_Vl);

    cudaFuncSetAttribute(gemm_bf16_mma, cudaFuncAttributeMaxDynamicSharedMemorySize, GEMM_SMEM);
    cudaFuncSetAttribute(attn_mma, cudaFuncAttributeMaxDynamicSharedMemorySize, ATTN_SMEM);

    const float qscale = 0.08838834764831845f;   // 1/sqrt(128)

    conv_act<<<(MTOK * DMODEL) / 256, 256>>>(inputs_q,  aq);
    conv_act<<<(MTOK * DMODEL) / 256, 256>>>(inputs_kv, akv);
    dim3 wtg(64, 64), wtb(32, 8);
    conv_wt<<<wtg, wtb>>>(Wq, wqt);
    conv_wt<<<wtg, wtb>>>(Wk, wkt);
    conv_wt<<<wtg, wtb>>>(Wv, wvt);
    conv_wt<<<wtg, wtb>>>(Wo, wot);

    dim3 gg(DMODEL / TBN, MTOK / TBM);           // (16, 64)
    gemm_bf16_mma<<<gg, 256, GEMM_SMEM>>>(aq,  wqt, nullptr, qh, ql, DMODEL, qscale);
    gemm_bf16_mma<<<gg, 256, GEMM_SMEM>>>(akv, wkt, nullptr, kh, kl, DMODEL, 1.0f);
    gemm_bf16_mma<<<gg, 256, GEMM_SMEM>>>(akv, wvt, nullptr, vh, vl, DMODEL, 1.0f);

    dim3 ag(S_LEN / 64, HEADS, BATCH);           // (16, 16, 8)
    attn_mma<<<ag, 128, ATTN_SMEM>>>(qh, ql, kh, kl, vh, vl, actx);

    gemm_bf16_mma<<<gg, 256, GEMM_SMEM>>>(actx, wot, out, nullptr, nullptr, DMODEL, 1.0f);
}

// round 9
// speedup vs baseline: 7.8690x; 1.6265x over previous
#include <cuda_runtime.h>
#include <cuda_fp16.h>
#include <cstdint>
#include <math.h>

// Problem dims
#define BATCH   8
#define S_LEN   1024
#define DMODEL  2048
#define HEADS   16
#define HD      128
#define MTOK    (BATCH * S_LEN)          // 8192 token rows
#define KROW    4096                     // activation row: [hi(2048) | lo(2048)]

// ---------------- scratch (device globals; no allocations allowed) ----------
__device__ __align__(16) __half g_Aq  [(size_t)MTOK * KROW];   // [hi | lo]
__device__ __align__(16) __half g_Akv [(size_t)MTOK * KROW];
__device__ __align__(16) __half g_Actx[(size_t)MTOK * KROW];
__device__ __align__(16) __half g_Wqt [(size_t)DMODEL * DMODEL]; // Wt[n][k] hi only
__device__ __align__(16) __half g_Wkt [(size_t)DMODEL * DMODEL];
__device__ __align__(16) __half g_Wvt [(size_t)DMODEL * DMODEL];
__device__ __align__(16) __half g_Wot [(size_t)DMODEL * DMODEL];
__device__ __align__(16) __half g_Qh [(size_t)MTOK * DMODEL];
__device__ __align__(16) __half g_Ql [(size_t)MTOK * DMODEL];
__device__ __align__(16) __half g_Kh [(size_t)MTOK * DMODEL];
__device__ __align__(16) __half g_Vh [(size_t)MTOK * DMODEL];

// ===================== PTX helpers ==========================================
__device__ __forceinline__ uint32_t smem_u32(const void* p) {
    uint32_t a;
    asm("{ .reg .u64 t; cvta.to.shared.u64 t, %1; cvt.u32.u64 %0, t; }" : "=r"(a) : "l"(p));
    return a;
}
__device__ __forceinline__ void cpasync16(uint32_t dst, const void* src) {
    asm volatile("cp.async.cg.shared.global [%0], [%1], 16;" :: "r"(dst), "l"(src) : "memory");
}
template <int N> __device__ __forceinline__ void cpwait() {
    asm volatile("cp.async.wait_group %0;" :: "n"(N) : "memory");
}
#define CPCOMMIT() asm volatile("cp.async.commit_group;" ::: "memory")

__device__ __forceinline__ void ldsm_x4(uint32_t* r, uint32_t addr) {
    asm volatile("ldmatrix.sync.aligned.m8n8.x4.shared.b16 {%0,%1,%2,%3}, [%4];"
        : "=r"(r[0]), "=r"(r[1]), "=r"(r[2]), "=r"(r[3]) : "r"(addr));
}
__device__ __forceinline__ void ldsm_x4_t(uint32_t* r, uint32_t addr) {
    asm volatile("ldmatrix.sync.aligned.m8n8.x4.trans.shared.b16 {%0,%1,%2,%3}, [%4];"
        : "=r"(r[0]), "=r"(r[1]), "=r"(r[2]), "=r"(r[3]) : "r"(addr));
}
__device__ __forceinline__ void mma16816(float* c, const uint32_t* a, uint32_t b0, uint32_t b1) {
    asm volatile("mma.sync.aligned.m16n8k16.row.col.f32.f16.f16.f32 "
        "{%0,%1,%2,%3}, {%4,%5,%6,%7}, {%8,%9}, {%0,%1,%2,%3};"
        : "+f"(c[0]), "+f"(c[1]), "+f"(c[2]), "+f"(c[3])
        : "r"(a[0]), "r"(a[1]), "r"(a[2]), "r"(a[3]), "r"(b0), "r"(b1));
}
__device__ __forceinline__ uint32_t packh2(float x, float y) {
    __half2 h = __floats2half2_rn(x, y);
    return *reinterpret_cast<uint32_t*>(&h);
}

// ===================== fp16 2-term split GEMM (B-tile reuse) ================
// C[M,N] = alpha * (Ah + Al)[M,K] * B[N,K]^T, K=2048; A row layout [hi|lo]
#define TBM 128
#define TBN 128
#define TBK 64
#define NITER (DMODEL / TBK)          // 32
#define ROW_B 144                     // smem row stride bytes (64 fp16 + 8 pad)
#define ATILE (128 * ROW_B)           // 18432
#define STAGE (3 * ATILE)             // 55296: Ah, Al, B
#define GEMM_SMEM (2 * STAGE)         // 110592, 2-stage, 2 CTA/SM

__global__ void __launch_bounds__(256, 2) gemm_fp16_mma(const __half* __restrict__ A,
                                                        const __half* __restrict__ B,
                                                        float* __restrict__ C,
                                                        __half* __restrict__ Ch,
                                                        __half* __restrict__ Cl,
                                                        float alpha)
{
    extern __shared__ char smc[];
    const uint32_t smem = smem_u32(smc);
    const int tid  = threadIdx.x;
    const int lane = tid & 31;
    const int wid  = tid >> 5;
    const int wm   = wid >> 2;        // 0..1 (64-row slab)
    const int wn   = wid & 3;         // 0..3 (32-col slab)

    const int m0 = blockIdx.y * TBM;
    const int n0 = blockIdx.x * TBN;

    float acc[4][4][4];
#pragma unroll
    for (int mi = 0; mi < 4; mi++)
#pragma unroll
        for (int ni = 0; ni < 4; ni++)
#pragma unroll
            for (int e = 0; e < 4; e++) acc[mi][ni][e] = 0.f;

    // stage = {Ah tile, Al tile, B tile}; 3072 16B chunks, 12 per thread
    auto load_stage = [&](int buf, int k0) {
#pragma unroll
        for (int t = 0; t < 12; t++) {
            int c    = tid + t * 256;
            int tile = c >> 10;            // 0=Ah 1=Al 2=B
            int cc   = c & 1023;
            int row  = cc >> 3, q = cc & 7;
            uint32_t off = (uint32_t)tile * ATILE + (uint32_t)(row * ROW_B + q * 16);
            const __half* g;
            if (tile == 2) g = B + (size_t)(n0 + row) * DMODEL + k0 + q * 8;
            else           g = A + (size_t)(m0 + row) * KROW + tile * DMODEL + k0 + q * 8;
            cpasync16(smem + buf * STAGE + off, g);
        }
        CPCOMMIT();
    };

    load_stage(0, 0);
    load_stage(1, TBK);

    for (int i = 0; i < NITER; i++) {
        const int buf = i & 1;
        if (i + 1 < NITER) cpwait<1>(); else cpwait<0>();
        __syncthreads();

        const uint32_t sah = smem + buf * STAGE + (uint32_t)(wm * 64) * ROW_B;
        const uint32_t sal = sah + ATILE;
        const uint32_t sb  = smem + buf * STAGE + 2 * ATILE + (uint32_t)(wn * 32) * ROW_B;

#pragma unroll
        for (int kh = 0; kh < 2; kh++) {
            uint32_t bfr[4][4];
#pragma unroll
            for (int ni = 0; ni < 4; ni++)
                ldsm_x4(bfr[ni], sb + (uint32_t)((ni * 8 + (lane & 7)) * ROW_B
                                                 + (kh * 32 + (lane >> 3) * 8) * 2));
#pragma unroll
            for (int kq = 0; kq < 2; kq++) {
                const uint32_t aoff = (uint32_t)((lane & 15)) * ROW_B
                                    + (uint32_t)(kh * 32 + kq * 16 + (lane >> 4) * 8) * 2;
                uint32_t afr[4][4];
#pragma unroll
                for (int mi = 0; mi < 4; mi++)
                    ldsm_x4(afr[mi], sah + (uint32_t)(mi * 16) * ROW_B + aoff);
#pragma unroll
                for (int mi = 0; mi < 4; mi++)
#pragma unroll
                    for (int ni = 0; ni < 4; ni++)
                        mma16816(acc[mi][ni], afr[mi], bfr[ni][2 * kq], bfr[ni][2 * kq + 1]);
#pragma unroll
                for (int mi = 0; mi < 4; mi++)
                    ldsm_x4(afr[mi], sal + (uint32_t)(mi * 16) * ROW_B + aoff);
#pragma unroll
                for (int mi = 0; mi < 4; mi++)
#pragma unroll
                    for (int ni = 0; ni < 4; ni++)
                        mma16816(acc[mi][ni], afr[mi], bfr[ni][2 * kq], bfr[ni][2 * kq + 1]);
            }
        }
        __syncthreads();
        if (i + 2 < NITER) load_stage(buf, (i + 2) * TBK);
    }

    // epilogue
#pragma unroll
    for (int mi = 0; mi < 4; mi++) {
#pragma unroll
        for (int ni = 0; ni < 4; ni++) {
            int r = m0 + wm * 64 + mi * 16 + (lane >> 2);
            int c = n0 + wn * 32 + ni * 8 + (lane & 3) * 2;
            float v0 = alpha * acc[mi][ni][0], v1 = alpha * acc[mi][ni][1];
            float v2 = alpha * acc[mi][ni][2], v3 = alpha * acc[mi][ni][3];
            if (Ch) {
                __half2 h0 = __floats2half2_rn(v0, v1);
                __half2 h1 = __floats2half2_rn(v2, v3);
                *(__half2*)(Ch + (size_t)r * DMODEL + c)       = h0;
                *(__half2*)(Ch + (size_t)(r + 8) * DMODEL + c) = h1;
                if (Cl) {
                    __half2 l0 = __floats2half2_rn(v0 - __low2float(h0), v1 - __high2float(h0));
                    __half2 l1 = __floats2half2_rn(v2 - __low2float(h1), v3 - __high2float(h1));
                    *(__half2*)(Cl + (size_t)r * DMODEL + c)       = l0;
                    *(__half2*)(Cl + (size_t)(r + 8) * DMODEL + c) = l1;
                }
            } else {
                *(float2*)(C + (size_t)r * DMODEL + c)       = make_float2(v0, v1);
                *(float2*)(C + (size_t)(r + 8) * DMODEL + c) = make_float2(v2, v3);
            }
        }
    }
}

// ===================== fp32 -> fp16 hi/lo split conversions =================
__global__ void __launch_bounds__(256) conv_act(const float* __restrict__ X,
                                                __half* __restrict__ Y)
{
    size_t idx = (size_t)blockIdx.x * 256 + threadIdx.x;
    float x = X[idx];
    __half h = __float2half_rn(x);
    __half l = __float2half_rn(x - __half2float(h));
    size_t row = idx >> 11;
    size_t col = idx & 2047;
    size_t base = row * KROW;
    Y[base + col] = h;
    Y[base + DMODEL + col] = l;
}

// W[k][n] fp32 -> Wt[n][k] fp16 (hi only)
__global__ void __launch_bounds__(256) conv_wt(const float* __restrict__ W,
                                               __half* __restrict__ Wt)
{
    __shared__ float tile[32][33];
    const int k0 = blockIdx.y * 32, n0 = blockIdx.x * 32;
    const int tx = threadIdx.x, ty = threadIdx.y;     // (32, 8)
#pragma unroll
    for (int i = 0; i < 4; i++)
        tile[ty + i * 8][tx] = W[(size_t)(k0 + ty + i * 8) * DMODEL + n0 + tx];
    __syncthreads();
#pragma unroll
    for (int i = 0; i < 4; i++) {
        int n = n0 + ty + i * 8;
        int k = k0 + tx;
        Wt[(size_t)n * DMODEL + k] = __float2half_rn(tile[tx][ty + i * 8]);
    }
}

// ============== Flash attention, fp16 2-term (Qh+Ql)Kh, (Ph+Pl)Vh ===========
// Grid (16,16,8); block 128 (4 warps, 16 q-rows each).
#define AT_STR 136                      // smem row stride (halfs), 272B
#define AT_TILE (64 * AT_STR)           // elems per tile
#define ATTN_SMEM (4 * AT_TILE * 2)     // QH QL KH VH

__global__ void __launch_bounds__(128, 2) attn_mma(
    const __half* __restrict__ Qh, const __half* __restrict__ Ql,
    const __half* __restrict__ Kh, const __half* __restrict__ Vh,
    __half* __restrict__ Actx)
{
    extern __shared__ char smc[];
    const uint32_t smem = smem_u32(smc);
    const int tid = threadIdx.x, lane = tid & 31, w = tid >> 5;
    const int q0 = blockIdx.x * 64, h = blockIdx.y, b = blockIdx.z;
    const size_t gbase = ((size_t)b * S_LEN) * DMODEL + (size_t)h * HD;
    const int qrow0 = w * 16;

    // load Q tiles once (hi, lo)
#pragma unroll
    for (int i = 0; i < 8; i++) {
        int id = tid + i * 128;
        int r = id >> 4, c = (id & 15) * 8;
        size_t g = gbase + (size_t)(q0 + r) * DMODEL + c;
        cpasync16(smem + (uint32_t)(0 * AT_TILE + r * AT_STR + c) * 2, Qh + g);
        cpasync16(smem + (uint32_t)(1 * AT_TILE + r * AT_STR + c) * 2, Ql + g);
    }
    CPCOMMIT();

    float m0 = -1e30f, m1 = -1e30f, l0 = 0.f, l1 = 0.f;
    float O[16][4];
#pragma unroll
    for (int i = 0; i < 16; i++)
#pragma unroll
        for (int e = 0; e < 4; e++) O[i][e] = 0.f;

    for (int kt = 0; kt < S_LEN / 64; kt++) {
        __syncthreads();
#pragma unroll
        for (int i = 0; i < 8; i++) {
            int id = tid + i * 128;
            int r = id >> 4, c = (id & 15) * 8;
            size_t g = gbase + (size_t)(kt * 64 + r) * DMODEL + c;
            uint32_t so = (uint32_t)(r * AT_STR + c) * 2;
            cpasync16(smem + 2 * AT_TILE * 2 + so, Kh + g);
            cpasync16(smem + 3 * AT_TILE * 2 + so, Vh + g);
        }
        CPCOMMIT();
        cpwait<0>();
        __syncthreads();

        // ---- scores: S[16 x 64] per warp, (Qh + Ql) * Kh ----
        float S[8][4];
#pragma unroll
        for (int ni = 0; ni < 8; ni++)
#pragma unroll
            for (int e = 0; e < 4; e++) S[ni][e] = 0.f;

#pragma unroll
        for (int kc = 0; kc < 16; kc++) {
            const int t  = kc >> 3;                 // 0: Qh*Kh 1: Ql*Kh
            const int k0 = (kc & 7) * 16;
            const uint32_t qtile = (uint32_t)(t * AT_TILE);
            uint32_t aq[4];
            {
                int row = qrow0 + (lane & 15);
                int col = k0 + (lane >> 4) * 8;
                ldsm_x4(aq, smem + (qtile + row * AT_STR + col) * 2);
            }
#pragma unroll
            for (int nb = 0; nb < 4; nb++) {
                uint32_t bk[4];
                int row = nb * 16 + ((lane >> 4) & 1) * 8 + (lane & 7);
                int col = k0 + ((lane >> 3) & 1) * 8;
                ldsm_x4(bk, smem + (uint32_t)(2 * AT_TILE + row * AT_STR + col) * 2);
                mma16816(S[2 * nb],     aq, bk[0], bk[1]);
                mma16816(S[2 * nb + 1], aq, bk[2], bk[3]);
            }
        }

        // ---- online softmax ----
        float mx0 = -1e30f, mx1 = -1e30f;
#pragma unroll
        for (int ni = 0; ni < 8; ni++) {
            mx0 = fmaxf(mx0, fmaxf(S[ni][0], S[ni][1]));
            mx1 = fmaxf(mx1, fmaxf(S[ni][2], S[ni][3]));
        }
        mx0 = fmaxf(mx0, __shfl_xor_sync(0xffffffff, mx0, 1));
        mx0 = fmaxf(mx0, __shfl_xor_sync(0xffffffff, mx0, 2));
        mx1 = fmaxf(mx1, __shfl_xor_sync(0xffffffff, mx1, 1));
        mx1 = fmaxf(mx1, __shfl_xor_sync(0xffffffff, mx1, 2));
        const float mn0 = fmaxf(m0, mx0), mn1 = fmaxf(m1, mx1);
        const float c0 = __expf(m0 - mn0), c1 = __expf(m1 - mn1);

        uint32_t Ph[16], Pl[16];
        float s0 = 0.f, s1 = 0.f;
#pragma unroll
        for (int ni = 0; ni < 8; ni++) {
            float p00 = __expf(S[ni][0] - mn0), p01 = __expf(S[ni][1] - mn0);
            float p10 = __expf(S[ni][2] - mn1), p11 = __expf(S[ni][3] - mn1);
            s0 += p00 + p01; s1 += p10 + p11;
            __half2 h0 = __floats2half2_rn(p00, p01);
            __half2 h1 = __floats2half2_rn(p10, p11);
            Ph[2 * ni]     = *reinterpret_cast<uint32_t*>(&h0);
            Ph[2 * ni + 1] = *reinterpret_cast<uint32_t*>(&h1);
            Pl[2 * ni]     = packh2(p00 - __low2float(h0), p01 - __high2float(h0));
            Pl[2 * ni + 1] = packh2(p10 - __low2float(h1), p11 - __high2float(h1));
        }
        s0 += __shfl_xor_sync(0xffffffff, s0, 1);
        s0 += __shfl_xor_sync(0xffffffff, s0, 2);
        s1 += __shfl_xor_sync(0xffffffff, s1, 1);
        s1 += __shfl_xor_sync(0xffffffff, s1, 2);
        l0 = l0 * c0 + s0; l1 = l1 * c1 + s1;
        m0 = mn0; m1 = mn1;

#pragma unroll
        for (int ni2 = 0; ni2 < 16; ni2++) {
            O[ni2][0] *= c0; O[ni2][1] *= c0;
            O[ni2][2] *= c1; O[ni2][3] *= c1;
        }

        // ---- PV: O += (Ph + Pl) * Vh ----
#pragma unroll
        for (int kc2 = 0; kc2 < 4; kc2++) {
            uint32_t ah[4] = {Ph[4 * kc2], Ph[4 * kc2 + 1], Ph[4 * kc2 + 2], Ph[4 * kc2 + 3]};
            uint32_t al[4] = {Pl[4 * kc2], Pl[4 * kc2 + 1], Pl[4 * kc2 + 2], Pl[4 * kc2 + 3]};
            const int k0 = kc2 * 16;
            const int vrow = k0 + ((lane >> 3) & 1) * 8 + (lane & 7);
#pragma unroll
            for (int vb = 0; vb < 8; vb++) {
                uint32_t bv[4];
                int col = vb * 16 + ((lane >> 4) & 1) * 8;
                ldsm_x4_t(bv, smem + (uint32_t)(3 * AT_TILE + vrow * AT_STR + col) * 2);
                mma16816(O[2 * vb],     ah, bv[0], bv[1]);
                mma16816(O[2 * vb + 1], ah, bv[2], bv[3]);
                mma16816(O[2 * vb],     al, bv[0], bv[1]);
                mma16816(O[2 * vb + 1], al, bv[2], bv[3]);
            }
        }
    }

    // ---- epilogue: normalize, split fp16 hi|lo, write Actx [hi|lo] ----
    const float inv0 = 1.f / l0, inv1 = 1.f / l1;
    const size_t tok0 = (size_t)b * S_LEN + q0 + qrow0 + (lane >> 2);
    const size_t tok1 = tok0 + 8;
#pragma unroll
    for (int ni2 = 0; ni2 < 16; ni2++) {
        int col = h * HD + ni2 * 8 + (lane & 3) * 2;
        float v00 = O[ni2][0] * inv0, v01 = O[ni2][1] * inv0;
        float v10 = O[ni2][2] * inv1, v11 = O[ni2][3] * inv1;
        __half2 h0 = __floats2half2_rn(v00, v01);
        __half2 h1 = __floats2half2_rn(v10, v11);
        __half2 lo0 = __floats2half2_rn(v00 - __low2float(h0), v01 - __high2float(h0));
        __half2 lo1 = __floats2half2_rn(v10 - __low2float(h1), v11 - __high2float(h1));
        __half* a0 = Actx + tok0 * KROW;
        __half* a1 = Actx + tok1 * KROW;
        *(__half2*)(a0 + col)          = h0;
        *(__half2*)(a0 + DMODEL + col) = lo0;
        *(__half2*)(a1 + col)          = h1;
        *(__half2*)(a1 + DMODEL + col) = lo1;
    }
}

// ---------------- launch ----------------------------------------------------
extern "C" void kernel_launch(void* const* d_in, const int* in_sizes, int n_in,
                              void* d_out, int out_size)
{
    const float* inputs_q  = (const float*)d_in[0];
    const float* inputs_kv = (const float*)d_in[1];
    const float* Wq        = (const float*)d_in[2];
    const float* Wk        = (const float*)d_in[3];
    const float* Wv        = (const float*)d_in[4];
    const float* Wo        = (const float*)d_in[5];
    float* out             = (float*)d_out;

    __half *aq, *akv, *actx, *wqt, *wkt, *wvt, *wot, *qh, *ql, *kh, *vh;
    cudaGetSymbolAddress((void**)&aq,  g_Aq);
    cudaGetSymbolAddress((void**)&akv, g_Akv);
    cudaGetSymbolAddress((void**)&actx,g_Actx);
    cudaGetSymbolAddress((void**)&wqt, g_Wqt);
    cudaGetSymbolAddress((void**)&wkt, g_Wkt);
    cudaGetSymbolAddress((void**)&wvt, g_Wvt);
    cudaGetSymbolAddress((void**)&wot, g_Wot);
    cudaGetSymbolAddress((void**)&qh, g_Qh);
    cudaGetSymbolAddress((void**)&ql, g_Ql);
    cudaGetSymbolAddress((void**)&kh, g_Kh);
    cudaGetSymbolAddress((void**)&vh, g_Vh);

    cudaFuncSetAttribute(gemm_fp16_mma, cudaFuncAttributeMaxDynamicSharedMemorySize, GEMM_SMEM);
    cudaFuncSetAttribute(attn_mma, cudaFuncAttributeMaxDynamicSharedMemorySize, ATTN_SMEM);

    const float qscale = 0.08838834764831845f;   // 1/sqrt(128)

    conv_act<<<(MTOK * DMODEL) / 256, 256>>>(inputs_q,  aq);
    conv_act<<<(MTOK * DMODEL) / 256, 256>>>(inputs_kv, akv);
    dim3 wtg(64, 64), wtb(32, 8);
    conv_wt<<<wtg, wtb>>>(Wq, wqt);
    conv_wt<<<wtg, wtb>>>(Wk, wkt);
    conv_wt<<<wtg, wtb>>>(Wv, wvt);
    conv_wt<<<wtg, wtb>>>(Wo, wot);

    dim3 gg(DMODEL / TBN, MTOK / TBM);           // (16, 64)
    gemm_fp16_mma<<<gg, 256, GEMM_SMEM>>>(aq,  wqt, nullptr, qh, ql, qscale);
    gemm_fp16_mma<<<gg, 256, GEMM_SMEM>>>(akv, wkt, nullptr, kh, nullptr, 1.0f);
    gemm_fp16_mma<<<gg, 256, GEMM_SMEM>>>(akv, wvt, nullptr, vh, nullptr, 1.0f);

    dim3 ag(S_LEN / 64, HEADS, BATCH);           // (16, 16, 8)
    attn_mma<<<ag, 128, ATTN_SMEM>>>(qh, ql, kh, vh, actx);

    gemm_fp16_mma<<<gg, 256, GEMM_SMEM>>>(actx, wot, out, nullptr, nullptr, 1.0f);
}

// round 13
// speedup vs baseline: 8.1631x; 1.0374x over previous
#include <cuda_runtime.h>
#include <cuda_fp16.h>
#include <cstdint>
#include <math.h>

// Problem dims
#define BATCH   8
#define S_LEN   1024
#define DMODEL  2048
#define HEADS   16
#define HD      128
#define MTOK    (BATCH * S_LEN)          // 8192 token rows
#define KROW    4096                     // activation row: [hi(2048) | lo(2048)]

// ---------------- scratch (device globals; no allocations allowed) ----------
__device__ __align__(16) __half g_Aq  [(size_t)MTOK * KROW];   // [hi | lo]
__device__ __align__(16) __half g_Akv [(size_t)MTOK * KROW];
__device__ __align__(16) __half g_Actx[(size_t)MTOK * KROW];
__device__ __align__(16) __half g_Wqt [(size_t)DMODEL * DMODEL];     // Wt[n][k] hi only
__device__ __align__(16) __half g_Wkvt[(size_t)2 * DMODEL * DMODEL]; // [Wk ; Wv] transposed
__device__ __align__(16) __half g_Wot [(size_t)DMODEL * DMODEL];
__device__ __align__(16) __half g_Qh [(size_t)MTOK * DMODEL];
__device__ __align__(16) __half g_Ql [(size_t)MTOK * DMODEL];
__device__ __align__(16) __half g_Kh [(size_t)MTOK * DMODEL];
__device__ __align__(16) __half g_Vh [(size_t)MTOK * DMODEL];

// ===================== PTX helpers ==========================================
__device__ __forceinline__ uint32_t smem_u32(const void* p) {
    uint32_t a;
    asm("{ .reg .u64 t; cvta.to.shared.u64 t, %1; cvt.u32.u64 %0, t; }" : "=r"(a) : "l"(p));
    return a;
}
__device__ __forceinline__ void cpasync16(uint32_t dst, const void* src) {
    asm volatile("cp.async.cg.shared.global [%0], [%1], 16;" :: "r"(dst), "l"(src) : "memory");
}
template <int N> __device__ __forceinline__ void cpwait() {
    asm volatile("cp.async.wait_group %0;" :: "n"(N) : "memory");
}
#define CPCOMMIT() asm volatile("cp.async.commit_group;" ::: "memory")

__device__ __forceinline__ void ldsm_x4(uint32_t* r, uint32_t addr) {
    asm volatile("ldmatrix.sync.aligned.m8n8.x4.shared.b16 {%0,%1,%2,%3}, [%4];"
        : "=r"(r[0]), "=r"(r[1]), "=r"(r[2]), "=r"(r[3]) : "r"(addr));
}
__device__ __forceinline__ void ldsm_x4_t(uint32_t* r, uint32_t addr) {
    asm volatile("ldmatrix.sync.aligned.m8n8.x4.trans.shared.b16 {%0,%1,%2,%3}, [%4];"
        : "=r"(r[0]), "=r"(r[1]), "=r"(r[2]), "=r"(r[3]) : "r"(addr));
}
__device__ __forceinline__ void mma16816(float* c, const uint32_t* a, uint32_t b0, uint32_t b1) {
    asm volatile("mma.sync.aligned.m16n8k16.row.col.f32.f16.f16.f32 "
        "{%0,%1,%2,%3}, {%4,%5,%6,%7}, {%8,%9}, {%0,%1,%2,%3};"
        : "+f"(c[0]), "+f"(c[1]), "+f"(c[2]), "+f"(c[3])
        : "r"(a[0]), "r"(a[1]), "r"(a[2]), "r"(a[3]), "r"(b0), "r"(b1));
}
__device__ __forceinline__ uint32_t packh2(float x, float y) {
    __half2 h = __floats2half2_rn(x, y);
    return *reinterpret_cast<uint32_t*>(&h);
}

// ===================== fp16 2-term split GEMM (B-tile reuse) ================
// C[M,N] = alpha * (Ah + Al)[M,K] * B[N',K]^T, K=2048; A row layout [hi|lo]
// Ch2 != null: split-output mode (cols >= DMODEL go to Ch2 at col-DMODEL).
#define TBM 128
#define TBN 128
#define TBK 64
#define NITER (DMODEL / TBK)          // 32
#define ROW_B 144                     // smem row stride bytes (64 fp16 + 8 pad)
#define ATILE (128 * ROW_B)           // 18432
#define STAGE (3 * ATILE)             // 55296: Ah, Al, B
#define GEMM_SMEM (2 * STAGE)         // 110592, 2-stage, 2 CTA/SM

__global__ void __launch_bounds__(256, 2) gemm_fp16_mma(const __half* __restrict__ A,
                                                        const __half* __restrict__ B,
                                                        float* __restrict__ C,
                                                        __half* __restrict__ Ch,
                                                        __half* __restrict__ Cl,
                                                        __half* __restrict__ Ch2,
                                                        float alpha)
{
    extern __shared__ char smc[];
    const uint32_t smem = smem_u32(smc);
    const int tid  = threadIdx.x;
    const int lane = tid & 31;
    const int wid  = tid >> 5;
    const int wm   = wid >> 2;        // 0..1 (64-row slab)
    const int wn   = wid & 3;         // 0..3 (32-col slab)

    const int m0 = blockIdx.y * TBM;
    const int n0 = blockIdx.x * TBN;

    float acc[4][4][4];
#pragma unroll
    for (int mi = 0; mi < 4; mi++)
#pragma unroll
        for (int ni = 0; ni < 4; ni++)
#pragma unroll
            for (int e = 0; e < 4; e++) acc[mi][ni][e] = 0.f;

    // stage = {Ah tile, Al tile, B tile}; 3072 16B chunks, 12 per thread
    auto load_stage = [&](int buf, int k0) {
#pragma unroll
        for (int t = 0; t < 12; t++) {
            int c    = tid + t * 256;
            int tile = c >> 10;            // 0=Ah 1=Al 2=B
            int cc   = c & 1023;
            int row  = cc >> 3, q = cc & 7;
            uint32_t off = (uint32_t)tile * ATILE + (uint32_t)(row * ROW_B + q * 16);
            const __half* g;
            if (tile == 2) g = B + (size_t)(n0 + row) * DMODEL + k0 + q * 8;
            else           g = A + (size_t)(m0 + row) * KROW + tile * DMODEL + k0 + q * 8;
            cpasync16(smem + buf * STAGE + off, g);
        }
        CPCOMMIT();
    };

    load_stage(0, 0);
    load_stage(1, TBK);

    for (int i = 0; i < NITER; i++) {
        const int buf = i & 1;
        if (i + 1 < NITER) cpwait<1>(); else cpwait<0>();
        __syncthreads();

        const uint32_t sah = smem + buf * STAGE + (uint32_t)(wm * 64) * ROW_B;
        const uint32_t sal = sah + ATILE;
        const uint32_t sb  = smem + buf * STAGE + 2 * ATILE + (uint32_t)(wn * 32) * ROW_B;

#pragma unroll
        for (int kh = 0; kh < 2; kh++) {
            uint32_t bfr[4][4];
#pragma unroll
            for (int ni = 0; ni < 4; ni++)
                ldsm_x4(bfr[ni], sb + (uint32_t)((ni * 8 + (lane & 7)) * ROW_B
                                                 + (kh * 32 + (lane >> 3) * 8) * 2));
#pragma unroll
            for (int kq = 0; kq < 2; kq++) {
                const uint32_t aoff = (uint32_t)((lane & 15)) * ROW_B
                                    + (uint32_t)(kh * 32 + kq * 16 + (lane >> 4) * 8) * 2;
                uint32_t afr[4][4];
#pragma unroll
                for (int mi = 0; mi < 4; mi++)
                    ldsm_x4(afr[mi], sah + (uint32_t)(mi * 16) * ROW_B + aoff);
#pragma unroll
                for (int mi = 0; mi < 4; mi++)
#pragma unroll
                    for (int ni = 0; ni < 4; ni++)
                        mma16816(acc[mi][ni], afr[mi], bfr[ni][2 * kq], bfr[ni][2 * kq + 1]);
#pragma unroll
                for (int mi = 0; mi < 4; mi++)
                    ldsm_x4(afr[mi], sal + (uint32_t)(mi * 16) * ROW_B + aoff);
#pragma unroll
                for (int mi = 0; mi < 4; mi++)
#pragma unroll
                    for (int ni = 0; ni < 4; ni++)
                        mma16816(acc[mi][ni], afr[mi], bfr[ni][2 * kq], bfr[ni][2 * kq + 1]);
            }
        }
        __syncthreads();
        if (i + 2 < NITER) load_stage(buf, (i + 2) * TBK);
    }

    // epilogue: select destination half for split-output (merged KV) mode
    __half* chp = Ch;
    int coff = 0;
    if (Ch2 != nullptr && n0 >= DMODEL) { chp = Ch2; coff = DMODEL; }

#pragma unroll
    for (int mi = 0; mi < 4; mi++) {
#pragma unroll
        for (int ni = 0; ni < 4; ni++) {
            int r = m0 + wm * 64 + mi * 16 + (lane >> 2);
            int c = n0 + wn * 32 + ni * 8 + (lane & 3) * 2 - coff;
            float v0 = alpha * acc[mi][ni][0], v1 = alpha * acc[mi][ni][1];
            float v2 = alpha * acc[mi][ni][2], v3 = alpha * acc[mi][ni][3];
            if (chp) {
                __half2 h0 = __floats2half2_rn(v0, v1);
                __half2 h1 = __floats2half2_rn(v2, v3);
                *(__half2*)(chp + (size_t)r * DMODEL + c)       = h0;
                *(__half2*)(chp + (size_t)(r + 8) * DMODEL + c) = h1;
                if (Cl) {
                    __half2 l0 = __floats2half2_rn(v0 - __low2float(h0), v1 - __high2float(h0));
                    __half2 l1 = __floats2half2_rn(v2 - __low2float(h1), v3 - __high2float(h1));
                    *(__half2*)(Cl + (size_t)r * DMODEL + c)       = l0;
                    *(__half2*)(Cl + (size_t)(r + 8) * DMODEL + c) = l1;
                }
            } else {
                *(float2*)(C + (size_t)r * DMODEL + c)       = make_float2(v0, v1);
                *(float2*)(C + (size_t)(r + 8) * DMODEL + c) = make_float2(v2, v3);
            }
        }
    }
}

// ===================== fp32 -> fp16 hi/lo split conversions =================
__global__ void __launch_bounds__(256) conv_act(const float* __restrict__ X,
                                                __half* __restrict__ Y)
{
    size_t idx = (size_t)blockIdx.x * 256 + threadIdx.x;
    float x = X[idx];
    __half h = __float2half_rn(x);
    __half l = __float2half_rn(x - __half2float(h));
    size_t row = idx >> 11;
    size_t col = idx & 2047;
    size_t base = row * KROW;
    Y[base + col] = h;
    Y[base + DMODEL + col] = l;
}

// W[k][n] fp32 -> Wt[n][k] fp16 (hi only)
__global__ void __launch_bounds__(256) conv_wt(const float* __restrict__ W,
                                               __half* __restrict__ Wt)
{
    __shared__ float tile[32][33];
    const int k0 = blockIdx.y * 32, n0 = blockIdx.x * 32;
    const int tx = threadIdx.x, ty = threadIdx.y;     // (32, 8)
#pragma unroll
    for (int i = 0; i < 4; i++)
        tile[ty + i * 8][tx] = W[(size_t)(k0 + ty + i * 8) * DMODEL + n0 + tx];
    __syncthreads();
#pragma unroll
    for (int i = 0; i < 4; i++) {
        int n = n0 + ty + i * 8;
        int k = k0 + tx;
        Wt[(size_t)n * DMODEL + k] = __float2half_rn(tile[tx][ty + i * 8]);
    }
}

// ============== Flash attention, fp16 2-term, double-buffered K/V ===========
// Grid (16,16,8); block 128 (4 warps, 16 q-rows each).
// smem tiles: 0=QH 1=QL | buf0: 2=KH 3=VH | buf1: 4=KH 5=VH
#define AT_STR 136                      // smem row stride (halfs), 272B
#define AT_TILE (64 * AT_STR)           // elems per tile
#define ATTN_SMEM (6 * AT_TILE * 2)     // 104448 B -> 2 CTA/SM

__global__ void __launch_bounds__(128, 2) attn_mma(
    const __half* __restrict__ Qh, const __half* __restrict__ Ql,
    const __half* __restrict__ Kh, const __half* __restrict__ Vh,
    __half* __restrict__ Actx)
{
    extern __shared__ char smc[];
    const uint32_t smem = smem_u32(smc);
    const int tid = threadIdx.x, lane = tid & 31, w = tid >> 5;
    const int q0 = blockIdx.x * 64, h = blockIdx.y, b = blockIdx.z;
    const size_t gbase = ((size_t)b * S_LEN) * DMODEL + (size_t)h * HD;
    const int qrow0 = w * 16;

    // K/V tile loader into buffer cb (0/1)
    auto load_kv = [&](int cb, int kt) {
        const uint32_t kb = (uint32_t)(2 + 2 * cb) * AT_TILE * 2;
        const uint32_t vb = kb + AT_TILE * 2;
#pragma unroll
        for (int i = 0; i < 8; i++) {
            int id = tid + i * 128;
            int r = id >> 4, c = (id & 15) * 8;
            size_t g = gbase + (size_t)(kt * 64 + r) * DMODEL + c;
            uint32_t so = (uint32_t)(r * AT_STR + c) * 2;
            cpasync16(smem + kb + so, Kh + g);
            cpasync16(smem + vb + so, Vh + g);
        }
        CPCOMMIT();
    };

    // load Q tiles once (hi, lo), then prefetch KV tile 0
#pragma unroll
    for (int i = 0; i < 8; i++) {
        int id = tid + i * 128;
        int r = id >> 4, c = (id & 15) * 8;
        size_t g = gbase + (size_t)(q0 + r) * DMODEL + c;
        cpasync16(smem + (uint32_t)(0 * AT_TILE + r * AT_STR + c) * 2, Qh + g);
        cpasync16(smem + (uint32_t)(1 * AT_TILE + r * AT_STR + c) * 2, Ql + g);
    }
    CPCOMMIT();
    load_kv(0, 0);

    float m0 = -1e30f, m1 = -1e30f, l0 = 0.f, l1 = 0.f;
    float O[16][4];
#pragma unroll
    for (int i = 0; i < 16; i++)
#pragma unroll
        for (int e = 0; e < 4; e++) O[i][e] = 0.f;

    for (int kt = 0; kt < S_LEN / 64; kt++) {
        const int cb = kt & 1;
        if (kt + 1 < S_LEN / 64) { load_kv(cb ^ 1, kt + 1); cpwait<1>(); }
        else                     cpwait<0>();
        __syncthreads();

        const uint32_t ktile = (uint32_t)(2 + 2 * cb) * AT_TILE;
        const uint32_t vtile = ktile + AT_TILE;

        // ---- scores: S[16 x 64] per warp, (Qh + Ql) * Kh ----
        float S[8][4];
#pragma unroll
        for (int ni = 0; ni < 8; ni++)
#pragma unroll
            for (int e = 0; e < 4; e++) S[ni][e] = 0.f;

#pragma unroll
        for (int kc = 0; kc < 16; kc++) {
            const int t  = kc >> 3;                 // 0: Qh*Kh 1: Ql*Kh
            const int k0 = (kc & 7) * 16;
            const uint32_t qtile = (uint32_t)(t * AT_TILE);
            uint32_t aq[4];
            {
                int row = qrow0 + (lane & 15);
                int col = k0 + (lane >> 4) * 8;
                ldsm_x4(aq, smem + (qtile + row * AT_STR + col) * 2);
            }
#pragma unroll
            for (int nb = 0; nb < 4; nb++) {
                uint32_t bk[4];
                int row = nb * 16 + ((lane >> 4) & 1) * 8 + (lane & 7);
                int col = k0 + ((lane >> 3) & 1) * 8;
                ldsm_x4(bk, smem + (ktile + row * AT_STR + col) * 2);
                mma16816(S[2 * nb],     aq, bk[0], bk[1]);
                mma16816(S[2 * nb + 1], aq, bk[2], bk[3]);
            }
        }

        // ---- online softmax ----
        float mx0 = -1e30f, mx1 = -1e30f;
#pragma unroll
        for (int ni = 0; ni < 8; ni++) {
            mx0 = fmaxf(mx0, fmaxf(S[ni][0], S[ni][1]));
            mx1 = fmaxf(mx1, fmaxf(S[ni][2], S[ni][3]));
        }
        mx0 = fmaxf(mx0, __shfl_xor_sync(0xffffffff, mx0, 1));
        mx0 = fmaxf(mx0, __shfl_xor_sync(0xffffffff, mx0, 2));
        mx1 = fmaxf(mx1, __shfl_xor_sync(0xffffffff, mx1, 1));
        mx1 = fmaxf(mx1, __shfl_xor_sync(0xffffffff, mx1, 2));
        const float mn0 = fmaxf(m0, mx0), mn1 = fmaxf(m1, mx1);
        const float c0 = __expf(m0 - mn0), c1 = __expf(m1 - mn1);

        uint32_t Ph[16], Pl[16];
        float s0 = 0.f, s1 = 0.f;
#pragma unroll
        for (int ni = 0; ni < 8; ni++) {
            float p00 = __expf(S[ni][0] - mn0), p01 = __expf(S[ni][1] - mn0);
            float p10 = __expf(S[ni][2] - mn1), p11 = __expf(S[ni][3] - mn1);
            s0 += p00 + p01; s1 += p10 + p11;
            __half2 h0 = __floats2half2_rn(p00, p01);
            __half2 h1 = __floats2half2_rn(p10, p11);
            Ph[2 * ni]     = *reinterpret_cast<uint32_t*>(&h0);
            Ph[2 * ni + 1] = *reinterpret_cast<uint32_t*>(&h1);
            Pl[2 * ni]     = packh2(p00 - __low2float(h0), p01 - __high2float(h0));
            Pl[2 * ni + 1] = packh2(p10 - __low2float(h1), p11 - __high2float(h1));
        }
        s0 += __shfl_xor_sync(0xffffffff, s0, 1);
        s0 += __shfl_xor_sync(0xffffffff, s0, 2);
        s1 += __shfl_xor_sync(0xffffffff, s1, 1);
        s1 += __shfl_xor_sync(0xffffffff, s1, 2);
        l0 = l0 * c0 + s0; l1 = l1 * c1 + s1;
        m0 = mn0; m1 = mn1;

#pragma unroll
        for (int ni2 = 0; ni2 < 16; ni2++) {
            O[ni2][0] *= c0; O[ni2][1] *= c0;
            O[ni2][2] *= c1; O[ni2][3] *= c1;
        }

        // ---- PV: O += (Ph + Pl) * Vh ----
#pragma unroll
        for (int kc2 = 0; kc2 < 4; kc2++) {
            uint32_t ah[4] = {Ph[4 * kc2], Ph[4 * kc2 + 1], Ph[4 * kc2 + 2], Ph[4 * kc2 + 3]};
            uint32_t al[4] = {Pl[4 * kc2], Pl[4 * kc2 + 1], Pl[4 * kc2 + 2], Pl[4 * kc2 + 3]};
            const int k0 = kc2 * 16;
            const int vrow = k0 + ((lane >> 3) & 1) * 8 + (lane & 7);
#pragma unroll
            for (int vb = 0; vb < 8; vb++) {
                uint32_t bv[4];
                int col = vb * 16 + ((lane >> 4) & 1) * 8;
                ldsm_x4_t(bv, smem + (vtile + vrow * AT_STR + col) * 2);
                mma16816(O[2 * vb],     ah, bv[0], bv[1]);
                mma16816(O[2 * vb + 1], ah, bv[2], bv[3]);
                mma16816(O[2 * vb],     al, bv[0], bv[1]);
                mma16816(O[2 * vb + 1], al, bv[2], bv[3]);
            }
        }
        __syncthreads();   // all warps done reading this buffer before next prefetch overwrites
    }

    // ---- epilogue: normalize, split fp16 hi|lo, write Actx [hi|lo] ----
    const float inv0 = 1.f / l0, inv1 = 1.f / l1;
    const size_t tok0 = (size_t)b * S_LEN + q0 + qrow0 + (lane >> 2);
    const size_t tok1 = tok0 + 8;
#pragma unroll
    for (int ni2 = 0; ni2 < 16; ni2++) {
        int col = h * HD + ni2 * 8 + (lane & 3) * 2;
        float v00 = O[ni2][0] * inv0, v01 = O[ni2][1] * inv0;
        float v10 = O[ni2][2] * inv1, v11 = O[ni2][3] * inv1;
        __half2 h0 = __floats2half2_rn(v00, v01);
        __half2 h1 = __floats2half2_rn(v10, v11);
        __half2 lo0 = __floats2half2_rn(v00 - __low2float(h0), v01 - __high2float(h0));
        __half2 lo1 = __floats2half2_rn(v10 - __low2float(h1), v11 - __high2float(h1));
        __half* a0 = Actx + tok0 * KROW;
        __half* a1 = Actx + tok1 * KROW;
        *(__half2*)(a0 + col)          = h0;
        *(__half2*)(a0 + DMODEL + col) = lo0;
        *(__half2*)(a1 + col)          = h1;
        *(__half2*)(a1 + DMODEL + col) = lo1;
    }
}

// ---------------- launch ----------------------------------------------------
extern "C" void kernel_launch(void* const* d_in, const int* in_sizes, int n_in,
                              void* d_out, int out_size)
{
    const float* inputs_q  = (const float*)d_in[0];
    const float* inputs_kv = (const float*)d_in[1];
    const float* Wq        = (const float*)d_in[2];
    const float* Wk        = (const float*)d_in[3];
    const float* Wv        = (const float*)d_in[4];
    const float* Wo        = (const float*)d_in[5];
    float* out             = (float*)d_out;

    __half *aq, *akv, *actx, *wqt, *wkvt, *wot, *qh, *ql, *kh, *vh;
    cudaGetSymbolAddress((void**)&aq,  g_Aq);
    cudaGetSymbolAddress((void**)&akv, g_Akv);
    cudaGetSymbolAddress((void**)&actx,g_Actx);
    cudaGetSymbolAddress((void**)&wqt, g_Wqt);
    cudaGetSymbolAddress((void**)&wkvt,g_Wkvt);
    cudaGetSymbolAddress((void**)&wot, g_Wot);
    cudaGetSymbolAddress((void**)&qh, g_Qh);
    cudaGetSymbolAddress((void**)&ql, g_Ql);
    cudaGetSymbolAddress((void**)&kh, g_Kh);
    cudaGetSymbolAddress((void**)&vh, g_Vh);

    cudaFuncSetAttribute(gemm_fp16_mma, cudaFuncAttributeMaxDynamicSharedMemorySize, GEMM_SMEM);
    cudaFuncSetAttribute(attn_mma, cudaFuncAttributeMaxDynamicSharedMemorySize, ATTN_SMEM);

    const float qscale = 0.08838834764831845f;   // 1/sqrt(128)

    conv_act<<<(MTOK * DMODEL) / 256, 256>>>(inputs_q,  aq);
    conv_act<<<(MTOK * DMODEL) / 256, 256>>>(inputs_kv, akv);
    dim3 wtg(64, 64), wtb(32, 8);
    conv_wt<<<wtg, wtb>>>(Wq, wqt);
    conv_wt<<<wtg, wtb>>>(Wk, wkvt);
    conv_wt<<<wtg, wtb>>>(Wv, wkvt + (size_t)DMODEL * DMODEL);
    conv_wt<<<wtg, wtb>>>(Wo, wot);

    // Q projection (hi+lo out), merged K|V projection (hi out, split dest)
    dim3 gq(DMODEL / TBN, MTOK / TBM);           // (16, 64)
    dim3 gkv(2 * DMODEL / TBN, MTOK / TBM);      // (32, 64)
    gemm_fp16_mma<<<gq,  256, GEMM_SMEM>>>(aq,  wqt,  nullptr, qh, ql,      nullptr, qscale);
    gemm_fp16_mma<<<gkv, 256, GEMM_SMEM>>>(akv, wkvt, nullptr, kh, nullptr, vh,      1.0f);

    dim3 ag(S_LEN / 64, HEADS, BATCH);           // (16, 16, 8)
    attn_mma<<<ag, 128, ATTN_SMEM>>>(qh, ql, kh, vh, actx);

    gemm_fp16_mma<<<gq, 256, GEMM_SMEM>>>(actx, wot, out, nullptr, nullptr, nullptr, 1.0f);
}